// round 9
// baseline (speedup 1.0000x reference)
#include <cuda_runtime.h>
#include <cuda_bf16.h>
#include <math.h>
#include <stdint.h>

#define N_OBJ 2048
#define FDIM  2048
#define HDIM  1024
#define G6    6144          // 6*HDIM
#define KCAT  2048          // 2*HDIM
#define NCH   192           // 3 terms * (2048/32) k-chunks

// plane strides (elements)
#define PS_F  ((size_t)N_OBJ * FDIM)
#define PS_WX ((size_t)G6 * FDIM)
#define PS_WP ((size_t)HDIM * FDIM)
#define PS_WC ((size_t)G6 * KCAT)
#define PS_H  ((size_t)(N_OBJ + 1) * HDIM)

// 3-term expansion: a0b0 + a0b1 + a1b0  (a1b1 dropped, ~2^-18 relative)
#define TA_PACK 0x100u      // TA = {0,0,1}
#define TB_PACK 0x010u      // TB = {0,1,0}

// ---------------- scratch (static device globals; no allocation) -------------
__device__ float g_XG[(size_t)N_OBJ * G6];
__device__ float g_PX[(size_t)N_OBJ * HDIM];
__device__ float g_Wcat[(size_t)G6 * KCAT];          // fp32 (tiny-M path)
__device__ float g_biaslr[G6];
__device__ float g_C[(size_t)(N_OBJ + 1) * HDIM];
__device__ float g_H[(size_t)(N_OBJ + 1) * HDIM];
__device__ float g_Gh[(size_t)1024 * G6];            // split-K partial slabs

// bf16 split planes (2 planes each: hi, lo)
__device__ __nv_bfloat16 g_Fe [2 * PS_F];
__device__ __nv_bfloat16 g_Wxe[2 * PS_WX];
__device__ __nv_bfloat16 g_Wpe[2 * PS_WP];
__device__ __nv_bfloat16 g_Wce[2 * PS_WC];
__device__ __nv_bfloat16 g_He [2 * PS_H];

// ---------------- helpers ----------------------------------------------------
__device__ __forceinline__ uint32_t smem_to_u32(const void* p) {
    uint32_t a;
    asm("{ .reg .u64 t; cvta.to.shared.u64 t, %1; cvt.u32.u64 %0, t; }" : "=r"(a) : "l"(p));
    return a;
}
__device__ __forceinline__ void ldmx4(uint32_t* d, uint32_t addr) {
    asm volatile("ldmatrix.sync.aligned.m8n8.x4.shared.b16 {%0,%1,%2,%3}, [%4];"
                 : "=r"(d[0]), "=r"(d[1]), "=r"(d[2]), "=r"(d[3]) : "r"(addr));
}
__device__ __forceinline__ void mma_bf16(float* c, const uint32_t* a, const uint32_t* b) {
    asm volatile("mma.sync.aligned.m16n8k16.row.col.f32.bf16.bf16.f32 "
                 "{%0,%1,%2,%3}, {%4,%5,%6,%7}, {%8,%9}, {%0,%1,%2,%3};"
                 : "+f"(c[0]), "+f"(c[1]), "+f"(c[2]), "+f"(c[3])
                 : "r"(a[0]), "r"(a[1]), "r"(a[2]), "r"(a[3]), "r"(b[0]), "r"(b[1]));
}
__device__ __forceinline__ void cpasync16(uint32_t dst, const void* src) {
    asm volatile("cp.async.cg.shared.global [%0], [%1], 16;" :: "r"(dst), "l"(src));
}

// swizzle: 16B chunk x (0..3) within a 64B row r -> conflict-free for both
// cp.async stores and ldmatrix reads.
__device__ __forceinline__ uint32_t swz(int r, int x) {
    return (uint32_t)(r * 64 + ((x ^ ((r >> 1) & 3)) << 4));
}

// ---------------- bf16 double-split ------------------------------------------
__device__ __forceinline__ void bf16_split2(float x, __nv_bfloat16& t0, __nv_bfloat16& t1)
{
    t0 = __float2bfloat16(x);
    t1 = __float2bfloat16(x - __bfloat162float(t0));
}

// expand src fp32 [total] into 2 bf16 planes (hi, lo)
__global__ void expand_kernel(const float* __restrict__ src, __nv_bfloat16* __restrict__ dst,
                              size_t planeStride, int total)
{
    int i = blockIdx.x * 256 + threadIdx.x;
    if (i >= total) return;
    __nv_bfloat16 t0, t1;
    bf16_split2(src[i], t0, t1);
    dst[i] = t0;
    dst[planeStride + i] = t1;
}

// ---------------- prep: Wcat fp32, biaslr, sentinel rows ---------------------
__global__ void prep_kernel(const float* __restrict__ wl, const float* __restrict__ wr,
                            const float* __restrict__ bl, const float* __restrict__ br)
{
    int idx = blockIdx.x * 256 + threadIdx.x;   // over G6*KCAT
    int j = idx >> 11;
    int k = idx & (KCAT - 1);
    float w = (k < HDIM) ? wl[(size_t)j * HDIM + k] : wr[(size_t)j * HDIM + (k - HDIM)];
    g_Wcat[idx] = w;
    if (idx < G6) g_biaslr[idx] = bl[idx] + br[idx];
    if (idx < HDIM) {
        size_t s = (size_t)N_OBJ * HDIM + idx;
        g_C[s] = 0.f; g_H[s] = 0.f;
        __nv_bfloat16 z = __float2bfloat16(0.f);
        g_He[s] = z; g_He[PS_H + s] = z;
    }
}

// ---------------- bf16 mma GEMM: C = sum_t A[TA(t)] @ B[TB(t)]^T (+bias) -----
// A, B: 2 bf16 planes, row stride 2048 elems within each plane.
// BM=BN=128, BK=32, 4-stage cp.async pipeline, ldmatrix fragments.
// Split-K: blockIdx.z = part; part p handles chunks [p*cpp, (p+1)*cpp) and
// writes its own output slab C + p*M*N. Deterministic (no atomics).
__global__ __launch_bounds__(256, 2) void gemm_bf(
    const __nv_bfloat16* __restrict__ A, size_t psA,
    const __nv_bfloat16* __restrict__ B, size_t psB,
    const float* __restrict__ bias, float* __restrict__ C, int M, int N, int cpp)
{
    extern __shared__ char smem[];
    const uint32_t sb = smem_to_u32(smem);
    const int tid = threadIdx.x, lane = tid & 31, warp = tid >> 5;
    const int wr_ = warp >> 2, wc_ = warp & 3;            // 2 x 4 warp grid

    const int part = blockIdx.z;
    C += (size_t)part * M * N;
    const int c0 = part * cpp;

    // ---- L2-aware tile swizzle (within a part) ----
    const int tiles_n = gridDim.x, tiles_m = gridDim.y;
    int lid = blockIdx.y * tiles_n + blockIdx.x;
    const int GRP = 8;
    int per_group = GRP * tiles_m;
    int grp = lid / per_group, rem = lid - grp * per_group;
    int nt0 = grp * GRP;
    int gn = tiles_n - nt0; if (gn > GRP) gn = GRP;
    int nt = nt0 + rem % gn;
    int mt = rem / gn;
    const int row0 = mt * 128, col0 = nt * 128;

    // ldmatrix lane geometry
    const int lrow = ((lane >> 3) & 1) * 8 + (lane & 7);
    const int lcol = lane >> 4;

    // cp.async op coords
    const int r_op0 = tid >> 2,         ch0 = tid & 3;
    const int r_op1 = (tid + 256) >> 2, ch1 = tid & 3;

    float acc[4][4][4];
#pragma unroll
    for (int a = 0; a < 4; a++)
#pragma unroll
        for (int b = 0; b < 4; b++)
#pragma unroll
            for (int t = 0; t < 4; t++) acc[a][b][t] = 0.f;

    auto load_chunk = [&](int c, int st) {
        int t = c >> 6;
        size_t pa = (size_t)((TA_PACK >> (4 * t)) & 0xF) * psA;
        size_t pb = (size_t)((TB_PACK >> (4 * t)) & 0xF) * psB;
        const __nv_bfloat16* Ab = A + pa + (size_t)(c & 63) * 32;
        const __nv_bfloat16* Bb = B + pb + (size_t)(c & 63) * 32;
        uint32_t sA = sb + st * 16384, sBm = sA + 8192;
        cpasync16(sA  + swz(r_op0, ch0), Ab + (size_t)(row0 + r_op0) * 2048 + ch0 * 8);
        cpasync16(sA  + swz(r_op1, ch1), Ab + (size_t)(row0 + r_op1) * 2048 + ch1 * 8);
        cpasync16(sBm + swz(r_op0, ch0), Bb + (size_t)(col0 + r_op0) * 2048 + ch0 * 8);
        cpasync16(sBm + swz(r_op1, ch1), Bb + (size_t)(col0 + r_op1) * 2048 + ch1 * 8);
        asm volatile("cp.async.commit_group;" ::: "memory");
    };

    load_chunk(c0, 0); load_chunk(c0 + 1, 1); load_chunk(c0 + 2, 2);

    for (int i = 0; i < cpp; i++) {
        int st = i & 3;
        if (i + 3 < cpp) {
            asm volatile("cp.async.wait_group 2;" ::: "memory");
        } else {
            asm volatile("cp.async.wait_group 0;" ::: "memory");   // tail drain
        }
        __syncthreads();
        if (i + 3 < cpp) load_chunk(c0 + i + 3, (i + 3) & 3);

        uint32_t sA = sb + st * 16384, sBm = sA + 8192;
#pragma unroll
        for (int kk = 0; kk < 2; kk++) {
            uint32_t af[4][4], bq[2][4];
#pragma unroll
            for (int mf = 0; mf < 4; mf++) {
                int r = wr_ * 64 + mf * 16 + lrow;
                ldmx4(af[mf], sA + swz(r, lcol + kk * 2));
            }
#pragma unroll
            for (int bh = 0; bh < 2; bh++) {
                int r = wc_ * 32 + bh * 16 + lrow;
                ldmx4(bq[bh], sBm + swz(r, lcol + kk * 2));
            }
#pragma unroll
            for (int mf = 0; mf < 4; mf++)
#pragma unroll
                for (int nf = 0; nf < 4; nf++) {
                    uint32_t b2[2] = { bq[nf >> 1][nf & 1], bq[nf >> 1][2 + (nf & 1)] };
                    mma_bf16(acc[mf][nf], af[mf], b2);
                }
        }
    }

    // ---- epilogue ----
#pragma unroll
    for (int mf = 0; mf < 4; mf++) {
#pragma unroll
        for (int nf = 0; nf < 4; nf++) {
            int r  = row0 + wr_ * 64 + mf * 16 + (lane >> 2);
            int cb = col0 + wc_ * 32 + nf * 8 + (lane & 3) * 2;
            float b0 = bias ? bias[cb] : 0.f;
            float b1 = bias ? bias[cb + 1] : 0.f;
            if (r < M) {
                C[(size_t)r * N + cb]     = acc[mf][nf][0] + b0;
                C[(size_t)r * N + cb + 1] = acc[mf][nf][1] + b1;
            }
            if (r + 8 < M) {
                C[(size_t)(r + 8) * N + cb]     = acc[mf][nf][2] + b0;
                C[(size_t)(r + 8) * N + cb + 1] = acc[mf][nf][3] + b1;
            }
        }
    }
}

// ---------------- tiny-M GEMM (M<=16): one warp per output column n ---------
__global__ void gemm_small(const float* __restrict__ A, const float* __restrict__ B,
                           float* __restrict__ C, int M, int N, int K)
{
    int warp = threadIdx.x >> 5, lane = threadIdx.x & 31;
    int n = blockIdx.x * 8 + warp;
    if (n >= N) return;
    float acc[16];
#pragma unroll
    for (int m = 0; m < 16; m++) acc[m] = 0.f;
    const float* Brow = B + (size_t)n * K;
    for (int k = lane * 4; k < K; k += 128) {
        float4 bv = *(const float4*)(Brow + k);
#pragma unroll
        for (int m = 0; m < 16; m++) {
            if (m < M) {
                float4 av = *(const float4*)(A + (size_t)m * K + k);
                acc[m] += av.x * bv.x + av.y * bv.y + av.z * bv.z + av.w * bv.w;
            }
        }
    }
#pragma unroll
    for (int m = 0; m < 16; m++) {
        if (m < M) {
            float v = acc[m];
#pragma unroll
            for (int off = 16; off; off >>= 1) v += __shfl_xor_sync(~0u, v, off);
            if (lane == 0) C[(size_t)m * N + n] = v;
        }
    }
}

// ---------------- pointwise LSTM cell for one wavefront ----------------------
__device__ __forceinline__ float sigm(float x) { return 1.f / (1.f + expf(-x)); }

__global__ void pointwise(int s, int M, const float* __restrict__ Gh,
                          int nparts, int pstride)
{
    int idx = blockIdx.x * blockDim.x + threadIdx.x;
    if (idx >= M * HDIM) return;
    int m = idx >> 10;
    int j = idx & (HDIM - 1);
    int n = s + m;

    const float* xg = g_XG + (size_t)n * G6;
    float g[6];
#pragma unroll
    for (int t = 0; t < 6; t++) {
        int o = t * HDIM + j;
        float v = xg[o] + g_biaslr[o];
        for (int p = 0; p < nparts; p++)
            v += Gh[(size_t)p * pstride + (size_t)m * G6 + o];
        g[t] = v;
    }
    float ig = sigm(g[0]), og = sigm(g[1]);
    float fl = sigm(g[2]), fr = sigm(g[3]);
    float u  = tanhf(g[4]), rr = sigm(g[5]);

    int l = 2 * n + 1; if (l > N_OBJ) l = N_OBJ;
    int r = 2 * n + 2; if (r > N_OBJ) r = N_OBJ;

    float c = ig * u + fl * g_C[(size_t)l * HDIM + j] + fr * g_C[(size_t)r * HDIM + j];
    float h = og * tanhf(c);
    float hf = rr * h + (1.f - rr) * g_PX[(size_t)n * HDIM + j];

    size_t o = (size_t)n * HDIM + j;
    g_C[o] = c;
    g_H[o] = hf;
    __nv_bfloat16 t0, t1;
    bf16_split2(hf, t0, t1);
    g_He[o] = t0; g_He[PS_H + o] = t1;
}

// ---------------- final copy -------------------------------------------------
__global__ void copyout(float* __restrict__ out)
{
    int idx = blockIdx.x * 256 + threadIdx.x;
    ((float4*)out)[idx] = ((const float4*)g_H)[idx];
}

// ---------------- launcher ---------------------------------------------------
extern "C" void kernel_launch(void* const* d_in, const int* in_sizes, int n_in,
                              void* d_out, int out_size)
{
    const float* features = (const float*)d_in[0];
    const float* w_iox    = (const float*)d_in[1];
    const float* b_iox    = (const float*)d_in[2];
    const float* w_l      = (const float*)d_in[3];
    const float* b_l      = (const float*)d_in[4];
    const float* w_r      = (const float*)d_in[5];
    const float* b_r      = (const float*)d_in[6];
    const float* w_px     = (const float*)d_in[7];
    const float* b_px     = (const float*)d_in[8];

    float *XG, *PX, *Wcat, *Gh, *Htab;
    __nv_bfloat16 *Fe, *Wxe, *Wpe, *Wce, *He;
    cudaGetSymbolAddress((void**)&XG,   g_XG);
    cudaGetSymbolAddress((void**)&PX,   g_PX);
    cudaGetSymbolAddress((void**)&Wcat, g_Wcat);
    cudaGetSymbolAddress((void**)&Gh,   g_Gh);
    cudaGetSymbolAddress((void**)&Htab, g_H);
    cudaGetSymbolAddress((void**)&Fe,   g_Fe);
    cudaGetSymbolAddress((void**)&Wxe,  g_Wxe);
    cudaGetSymbolAddress((void**)&Wpe,  g_Wpe);
    cudaGetSymbolAddress((void**)&Wce,  g_Wce);
    cudaGetSymbolAddress((void**)&He,   g_He);

    const int SMEM_TC = 4 * 16384;
    cudaFuncSetAttribute(gemm_bf, cudaFuncAttributeMaxDynamicSharedMemorySize, SMEM_TC);

    // prep + operand 2-plane expansion
    prep_kernel<<<(G6 * KCAT) / 256, 256>>>(w_l, w_r, b_l, b_r);
    expand_kernel<<<(int)((PS_F  + 255) / 256), 256>>>(features, Fe,  PS_F,  (int)PS_F);
    expand_kernel<<<(int)((PS_WX + 255) / 256), 256>>>(w_iox,    Wxe, PS_WX, (int)PS_WX);
    expand_kernel<<<(int)((PS_WP + 255) / 256), 256>>>(w_px,     Wpe, PS_WP, (int)PS_WP);
    expand_kernel<<<(int)((PS_WC + 255) / 256), 256>>>(Wcat,     Wce, PS_WC, (int)PS_WC);

    // phase A: x-gates and px (no split-K; full-chip grids)
    gemm_bf<<<dim3(G6 / 128,   N_OBJ / 128, 1), 256, SMEM_TC>>>(Fe, PS_F, Wxe, PS_WX, b_iox, XG, N_OBJ, G6,   NCH);
    gemm_bf<<<dim3(HDIM / 128, N_OBJ / 128, 1), 256, SMEM_TC>>>(Fe, PS_F, Wpe, PS_WP, b_px,  PX, N_OBJ, HDIM, NCH);

    // leaves
    pointwise<<<(1024 * HDIM + 255) / 256, 256>>>(1024, 1024, nullptr, 0, 0);

    // node 1023 (single, fp32 path; children rows 2047 + sentinel 2048)
    gemm_small<<<G6 / 8, 256>>>(Htab + (size_t)2047 * HDIM, Wcat, Gh, 1, G6, KCAT);
    pointwise<<<(1 * HDIM + 255) / 256, 256>>>(1023, 1, Gh, 1, 0);

    // big internal wavefronts with deterministic split-K
    struct Lv { int s, M, KS; };
    const Lv big[5] = { {511, 512, 2}, {255, 256, 4}, {127, 128, 8},
                        {63, 64, 8}, {31, 32, 8} };
    for (int li = 0; li < 5; li++) {
        int s = big[li].s, M = big[li].M, KS = big[li].KS;
        int Mtiles = (M + 127) / 128;
        const __nv_bfloat16* Ab = He + (size_t)(2 * s + 1) * HDIM;
        gemm_bf<<<dim3(G6 / 128, Mtiles, KS), 256, SMEM_TC>>>(
            Ab, PS_H, Wce, PS_WC, nullptr, Gh, M, G6, NCH / KS);
        pointwise<<<(M * HDIM + 255) / 256, 256>>>(s, M, Gh, KS, M * G6);
    }

    // tiny wavefronts (fp32 warp-dot)
    const Lv small_[5] = { {15, 16, 0}, {7, 8, 0}, {3, 4, 0}, {1, 2, 0}, {0, 1, 0} };
    for (int li = 0; li < 5; li++) {
        int s = small_[li].s, M = small_[li].M;
        gemm_small<<<G6 / 8, 256>>>(Htab + (size_t)(2 * s + 1) * HDIM, Wcat, Gh, M, G6, KCAT);
        pointwise<<<(M * HDIM + 255) / 256, 256>>>(s, M, Gh, 1, 0);
    }

    copyout<<<(N_OBJ * HDIM / 4) / 256, 256>>>((float*)d_out);
}

// round 10
// speedup vs baseline: 1.0291x; 1.0291x over previous
#include <cuda_runtime.h>
#include <cuda_bf16.h>
#include <math.h>
#include <stdint.h>

#define N_OBJ 2048
#define FDIM  2048
#define HDIM  1024
#define G6    6144          // 6*HDIM
#define KCAT  2048          // 2*HDIM
#define NCH   192           // 3 terms * (2048/32) k-chunks
#define NPAIR 96            // NCH / 2 (BK=64 stage pairs)

// plane strides (elements)
#define PS_F  ((size_t)N_OBJ * FDIM)
#define PS_WX ((size_t)G6 * FDIM)
#define PS_WP ((size_t)HDIM * FDIM)
#define PS_WC ((size_t)G6 * KCAT)
#define PS_H  ((size_t)(N_OBJ + 1) * HDIM)

// 3-term expansion: a0b0 + a0b1 + a1b0
#define TA_PACK 0x100u      // TA = {0,0,1}
#define TB_PACK 0x010u      // TB = {0,1,0}

// ---------------- scratch (static device globals; no allocation) -------------
__device__ float g_XG[(size_t)N_OBJ * G6];
__device__ float g_PX[(size_t)N_OBJ * HDIM];
__device__ float g_Wcat[(size_t)G6 * KCAT];          // fp32 (tiny-M path)
__device__ float g_biaslr[G6];
__device__ float g_C[(size_t)(N_OBJ + 1) * HDIM];
__device__ float g_H[(size_t)(N_OBJ + 1) * HDIM];
__device__ float g_Gh[(size_t)1024 * G6];            // split-K partial slabs

// bf16 split planes (2 planes each: hi, lo)
__device__ __nv_bfloat16 g_Fe [2 * PS_F];
__device__ __nv_bfloat16 g_Wxe[2 * PS_WX];
__device__ __nv_bfloat16 g_Wpe[2 * PS_WP];
__device__ __nv_bfloat16 g_Wce[2 * PS_WC];
__device__ __nv_bfloat16 g_He [2 * PS_H];

// ---------------- helpers ----------------------------------------------------
__device__ __forceinline__ uint32_t smem_to_u32(const void* p) {
    uint32_t a;
    asm("{ .reg .u64 t; cvta.to.shared.u64 t, %1; cvt.u32.u64 %0, t; }" : "=r"(a) : "l"(p));
    return a;
}
__device__ __forceinline__ void ldmx4(uint32_t* d, uint32_t addr) {
    asm volatile("ldmatrix.sync.aligned.m8n8.x4.shared.b16 {%0,%1,%2,%3}, [%4];"
                 : "=r"(d[0]), "=r"(d[1]), "=r"(d[2]), "=r"(d[3]) : "r"(addr));
}
__device__ __forceinline__ void mma_bf16(float* c, const uint32_t* a, const uint32_t* b) {
    asm volatile("mma.sync.aligned.m16n8k16.row.col.f32.bf16.bf16.f32 "
                 "{%0,%1,%2,%3}, {%4,%5,%6,%7}, {%8,%9}, {%0,%1,%2,%3};"
                 : "+f"(c[0]), "+f"(c[1]), "+f"(c[2]), "+f"(c[3])
                 : "r"(a[0]), "r"(a[1]), "r"(a[2]), "r"(a[3]), "r"(b[0]), "r"(b[1]));
}
__device__ __forceinline__ void cpasync16(uint32_t dst, const void* src) {
    asm volatile("cp.async.cg.shared.global [%0], [%1], 16;" :: "r"(dst), "l"(src));
}

// swizzle: 16B chunk x (0..3) within a 64B row r -> conflict-free for both
// cp.async stores and ldmatrix reads.
__device__ __forceinline__ uint32_t swz(int r, int x) {
    return (uint32_t)(r * 64 + ((x ^ ((r >> 1) & 3)) << 4));
}

// ---------------- bf16 double-split ------------------------------------------
__device__ __forceinline__ void bf16_split2(float x, __nv_bfloat16& t0, __nv_bfloat16& t1)
{
    t0 = __float2bfloat16(x);
    t1 = __float2bfloat16(x - __bfloat162float(t0));
}

// expand src fp32 [total] into 2 bf16 planes (hi, lo)
__global__ void expand_kernel(const float* __restrict__ src, __nv_bfloat16* __restrict__ dst,
                              size_t planeStride, int total)
{
    int i = blockIdx.x * 256 + threadIdx.x;
    if (i >= total) return;
    __nv_bfloat16 t0, t1;
    bf16_split2(src[i], t0, t1);
    dst[i] = t0;
    dst[planeStride + i] = t1;
}

// ---------------- prep: Wcat fp32, biaslr, sentinel rows ---------------------
__global__ void prep_kernel(const float* __restrict__ wl, const float* __restrict__ wr,
                            const float* __restrict__ bl, const float* __restrict__ br)
{
    int idx = blockIdx.x * 256 + threadIdx.x;   // over G6*KCAT
    int j = idx >> 11;
    int k = idx & (KCAT - 1);
    float w = (k < HDIM) ? wl[(size_t)j * HDIM + k] : wr[(size_t)j * HDIM + (k - HDIM)];
    g_Wcat[idx] = w;
    if (idx < G6) g_biaslr[idx] = bl[idx] + br[idx];
    if (idx < HDIM) {
        size_t s = (size_t)N_OBJ * HDIM + idx;
        g_C[s] = 0.f; g_H[s] = 0.f;
        __nv_bfloat16 z = __float2bfloat16(0.f);
        g_He[s] = z; g_He[PS_H + s] = z;
    }
}

// ---------------- bf16 mma GEMM: C = sum_t A[TA(t)] @ B[TB(t)]^T (+bias) -----
// A, B: 2 bf16 planes, row stride 2048 within each plane.
// Stage = BK64 = two 32-wide sub-tiles (A0,B0,A1,B1 @ 8KB each), 3 stages.
// One __syncthreads per 4 k16 steps; fragments double-buffered across k16.
// Split-K: blockIdx.z = part; part p handles pair range [p*ppp, (p+1)*ppp),
// writes slab C + p*M*N. Deterministic.
__global__ __launch_bounds__(256, 2) void gemm_bf(
    const __nv_bfloat16* __restrict__ A, size_t psA,
    const __nv_bfloat16* __restrict__ B, size_t psB,
    const float* __restrict__ bias, float* __restrict__ C, int M, int N, int ppp)
{
    extern __shared__ char smem[];
    const uint32_t sb = smem_to_u32(smem);
    const int tid = threadIdx.x, lane = tid & 31, warp = tid >> 5;
    const int wr_ = warp >> 2, wc_ = warp & 3;            // 2 x 4 warp grid

    const int part = blockIdx.z;
    C += (size_t)part * M * N;
    const int p0 = part * ppp;

    // ---- L2-aware tile swizzle (within a part) ----
    const int tiles_n = gridDim.x, tiles_m = gridDim.y;
    int lid = blockIdx.y * tiles_n + blockIdx.x;
    const int GRP = 8;
    int per_group = GRP * tiles_m;
    int grp = lid / per_group, rem = lid - grp * per_group;
    int nt0 = grp * GRP;
    int gn = tiles_n - nt0; if (gn > GRP) gn = GRP;
    int nt = nt0 + rem % gn;
    int mt = rem / gn;
    const int row0 = mt * 128, col0 = nt * 128;

    // ldmatrix lane geometry
    const int lrow = ((lane >> 3) & 1) * 8 + (lane & 7);
    const int lcol = lane >> 4;

    // cp.async op coords
    const int r_op0 = tid >> 2,         ch0 = tid & 3;
    const int r_op1 = (tid + 256) >> 2, ch1 = tid & 3;

    float acc[4][4][4];
#pragma unroll
    for (int a = 0; a < 4; a++)
#pragma unroll
        for (int b = 0; b < 4; b++)
#pragma unroll
            for (int t = 0; t < 4; t++) acc[a][b][t] = 0.f;

    // load one 32-wide chunk c into sub-slot (A @ off, B @ off+8192)
    auto load_sub = [&](int c, uint32_t off) {
        int t = c >> 6;
        size_t pa = (size_t)((TA_PACK >> (4 * t)) & 0xF) * psA;
        size_t pb = (size_t)((TB_PACK >> (4 * t)) & 0xF) * psB;
        const __nv_bfloat16* Ab = A + pa + (size_t)(c & 63) * 32;
        const __nv_bfloat16* Bb = B + pb + (size_t)(c & 63) * 32;
        uint32_t sA = sb + off, sBm = sA + 8192;
        cpasync16(sA  + swz(r_op0, ch0), Ab + (size_t)(row0 + r_op0) * 2048 + ch0 * 8);
        cpasync16(sA  + swz(r_op1, ch1), Ab + (size_t)(row0 + r_op1) * 2048 + ch1 * 8);
        cpasync16(sBm + swz(r_op0, ch0), Bb + (size_t)(col0 + r_op0) * 2048 + ch0 * 8);
        cpasync16(sBm + swz(r_op1, ch1), Bb + (size_t)(col0 + r_op1) * 2048 + ch1 * 8);
    };
    // load a BK64 pair p -> stage st (A0@0,B0@8K,A1@16K,B1@24K), one group
    auto load_pair = [&](int p, int st) {
        load_sub(2 * p,     (uint32_t)(st * 32768));
        load_sub(2 * p + 1, (uint32_t)(st * 32768 + 16384));
        asm volatile("cp.async.commit_group;" ::: "memory");
    };
    // fragment load for k16 step kk (0..3) of stage st
    auto ldfrag = [&](int st, int kk, uint32_t af[4][4], uint32_t bq[2][4]) {
        uint32_t sA = sb + st * 32768 + (kk >> 1) * 16384;
        uint32_t sBm = sA + 8192;
        int kl = (kk & 1) * 2 + lcol;
#pragma unroll
        for (int mf = 0; mf < 4; mf++) {
            int r = wr_ * 64 + mf * 16 + lrow;
            ldmx4(af[mf], sA + swz(r, kl));
        }
#pragma unroll
        for (int bh = 0; bh < 2; bh++) {
            int r = wc_ * 32 + bh * 16 + lrow;
            ldmx4(bq[bh], sBm + swz(r, kl));
        }
    };

    load_pair(p0, 0); load_pair(p0 + 1, 1);

    uint32_t fA[2][4][4], fB[2][2][4];

    for (int i = 0; i < ppp; i++) {
        int st = i % 3;
        if (i + 2 < ppp) {
            asm volatile("cp.async.wait_group 1;" ::: "memory");
        } else {
            asm volatile("cp.async.wait_group 0;" ::: "memory");   // tail drain
        }
        __syncthreads();
        if (i + 2 < ppp) load_pair(p0 + i + 2, (i + 2) % 3);

        ldfrag(st, 0, fA[0], fB[0]);
#pragma unroll
        for (int kk = 0; kk < 4; kk++) {
            if (kk < 3) ldfrag(st, kk + 1, fA[(kk + 1) & 1], fB[(kk + 1) & 1]);
            uint32_t (*af)[4] = fA[kk & 1];
            uint32_t (*bq)[4] = fB[kk & 1];
#pragma unroll
            for (int mf = 0; mf < 4; mf++)
#pragma unroll
                for (int nf = 0; nf < 4; nf++) {
                    uint32_t b2[2] = { bq[nf >> 1][nf & 1], bq[nf >> 1][2 + (nf & 1)] };
                    mma_bf16(acc[mf][nf], af[mf], b2);
                }
        }
    }

    // ---- epilogue ----
#pragma unroll
    for (int mf = 0; mf < 4; mf++) {
#pragma unroll
        for (int nf = 0; nf < 4; nf++) {
            int r  = row0 + wr_ * 64 + mf * 16 + (lane >> 2);
            int cb = col0 + wc_ * 32 + nf * 8 + (lane & 3) * 2;
            float b0 = bias ? bias[cb] : 0.f;
            float b1 = bias ? bias[cb + 1] : 0.f;
            if (r < M) {
                C[(size_t)r * N + cb]     = acc[mf][nf][0] + b0;
                C[(size_t)r * N + cb + 1] = acc[mf][nf][1] + b1;
            }
            if (r + 8 < M) {
                C[(size_t)(r + 8) * N + cb]     = acc[mf][nf][2] + b0;
                C[(size_t)(r + 8) * N + cb + 1] = acc[mf][nf][3] + b1;
            }
        }
    }
}

// ---------------- tiny-M GEMM (M<=16): one warp per output column n ---------
__global__ void gemm_small(const float* __restrict__ A, const float* __restrict__ B,
                           float* __restrict__ C, int M, int N, int K)
{
    int warp = threadIdx.x >> 5, lane = threadIdx.x & 31;
    int n = blockIdx.x * 8 + warp;
    if (n >= N) return;
    float acc[16];
#pragma unroll
    for (int m = 0; m < 16; m++) acc[m] = 0.f;
    const float* Brow = B + (size_t)n * K;
    for (int k = lane * 4; k < K; k += 128) {
        float4 bv = *(const float4*)(Brow + k);
#pragma unroll
        for (int m = 0; m < 16; m++) {
            if (m < M) {
                float4 av = *(const float4*)(A + (size_t)m * K + k);
                acc[m] += av.x * bv.x + av.y * bv.y + av.z * bv.z + av.w * bv.w;
            }
        }
    }
#pragma unroll
    for (int m = 0; m < 16; m++) {
        if (m < M) {
            float v = acc[m];
#pragma unroll
            for (int off = 16; off; off >>= 1) v += __shfl_xor_sync(~0u, v, off);
            if (lane == 0) C[(size_t)m * N + n] = v;
        }
    }
}

// ---------------- pointwise LSTM cell for one wavefront ----------------------
__device__ __forceinline__ float sigm(float x) { return 1.f / (1.f + expf(-x)); }

__global__ void pointwise(int s, int M, const float* __restrict__ Gh,
                          int nparts, int pstride)
{
    int idx = blockIdx.x * blockDim.x + threadIdx.x;
    if (idx >= M * HDIM) return;
    int m = idx >> 10;
    int j = idx & (HDIM - 1);
    int n = s + m;

    const float* xg = g_XG + (size_t)n * G6;
    float g[6];
#pragma unroll
    for (int t = 0; t < 6; t++) {
        int o = t * HDIM + j;
        float v = xg[o] + g_biaslr[o];
        for (int p = 0; p < nparts; p++)
            v += Gh[(size_t)p * pstride + (size_t)m * G6 + o];
        g[t] = v;
    }
    float ig = sigm(g[0]), og = sigm(g[1]);
    float fl = sigm(g[2]), fr = sigm(g[3]);
    float u  = tanhf(g[4]), rr = sigm(g[5]);

    int l = 2 * n + 1; if (l > N_OBJ) l = N_OBJ;
    int r = 2 * n + 2; if (r > N_OBJ) r = N_OBJ;

    float c = ig * u + fl * g_C[(size_t)l * HDIM + j] + fr * g_C[(size_t)r * HDIM + j];
    float h = og * tanhf(c);
    float hf = rr * h + (1.f - rr) * g_PX[(size_t)n * HDIM + j];

    size_t o = (size_t)n * HDIM + j;
    g_C[o] = c;
    g_H[o] = hf;
    __nv_bfloat16 t0, t1;
    bf16_split2(hf, t0, t1);
    g_He[o] = t0; g_He[PS_H + o] = t1;
}

// ---------------- final copy -------------------------------------------------
__global__ void copyout(float* __restrict__ out)
{
    int idx = blockIdx.x * 256 + threadIdx.x;
    ((float4*)out)[idx] = ((const float4*)g_H)[idx];
}

// ---------------- launcher ---------------------------------------------------
extern "C" void kernel_launch(void* const* d_in, const int* in_sizes, int n_in,
                              void* d_out, int out_size)
{
    const float* features = (const float*)d_in[0];
    const float* w_iox    = (const float*)d_in[1];
    const float* b_iox    = (const float*)d_in[2];
    const float* w_l      = (const float*)d_in[3];
    const float* b_l      = (const float*)d_in[4];
    const float* w_r      = (const float*)d_in[5];
    const float* b_r      = (const float*)d_in[6];
    const float* w_px     = (const float*)d_in[7];
    const float* b_px     = (const float*)d_in[8];

    float *XG, *PX, *Wcat, *Gh, *Htab;
    __nv_bfloat16 *Fe, *Wxe, *Wpe, *Wce, *He;
    cudaGetSymbolAddress((void**)&XG,   g_XG);
    cudaGetSymbolAddress((void**)&PX,   g_PX);
    cudaGetSymbolAddress((void**)&Wcat, g_Wcat);
    cudaGetSymbolAddress((void**)&Gh,   g_Gh);
    cudaGetSymbolAddress((void**)&Htab, g_H);
    cudaGetSymbolAddress((void**)&Fe,   g_Fe);
    cudaGetSymbolAddress((void**)&Wxe,  g_Wxe);
    cudaGetSymbolAddress((void**)&Wpe,  g_Wpe);
    cudaGetSymbolAddress((void**)&Wce,  g_Wce);
    cudaGetSymbolAddress((void**)&He,   g_He);

    const int SMEM_TC = 3 * 32768;
    cudaFuncSetAttribute(gemm_bf, cudaFuncAttributeMaxDynamicSharedMemorySize, SMEM_TC);

    // prep + operand 2-plane expansion
    prep_kernel<<<(G6 * KCAT) / 256, 256>>>(w_l, w_r, b_l, b_r);
    expand_kernel<<<(int)((PS_F  + 255) / 256), 256>>>(features, Fe,  PS_F,  (int)PS_F);
    expand_kernel<<<(int)((PS_WX + 255) / 256), 256>>>(w_iox,    Wxe, PS_WX, (int)PS_WX);
    expand_kernel<<<(int)((PS_WP + 255) / 256), 256>>>(w_px,     Wpe, PS_WP, (int)PS_WP);
    expand_kernel<<<(int)((PS_WC + 255) / 256), 256>>>(Wcat,     Wce, PS_WC, (int)PS_WC);

    // phase A: x-gates and px
    gemm_bf<<<dim3(G6 / 128,   N_OBJ / 128, 1), 256, SMEM_TC>>>(Fe, PS_F, Wxe, PS_WX, b_iox, XG, N_OBJ, G6,   NPAIR);
    gemm_bf<<<dim3(HDIM / 128, N_OBJ / 128, 1), 256, SMEM_TC>>>(Fe, PS_F, Wpe, PS_WP, b_px,  PX, N_OBJ, HDIM, NPAIR);

    // leaves
    pointwise<<<(1024 * HDIM + 255) / 256, 256>>>(1024, 1024, nullptr, 0, 0);

    // node 1023 (single, fp32 path; children rows 2047 + sentinel 2048)
    gemm_small<<<G6 / 8, 256>>>(Htab + (size_t)2047 * HDIM, Wcat, Gh, 1, G6, KCAT);
    pointwise<<<(1 * HDIM + 255) / 256, 256>>>(1023, 1, Gh, 1, 0);

    // big internal wavefronts with deterministic split-K
    struct Lv { int s, M, KS; };
    const Lv big[5] = { {511, 512, 2}, {255, 256, 4}, {127, 128, 8},
                        {63, 64, 8}, {31, 32, 8} };
    for (int li = 0; li < 5; li++) {
        int s = big[li].s, M = big[li].M, KS = big[li].KS;
        int Mtiles = (M + 127) / 128;
        const __nv_bfloat16* Ab = He + (size_t)(2 * s + 1) * HDIM;
        gemm_bf<<<dim3(G6 / 128, Mtiles, KS), 256, SMEM_TC>>>(
            Ab, PS_H, Wce, PS_WC, nullptr, Gh, M, G6, NPAIR / KS);
        pointwise<<<(M * HDIM + 255) / 256, 256>>>(s, M, Gh, KS, M * G6);
    }

    // tiny wavefronts (fp32 warp-dot)
    const Lv small_[5] = { {15, 16, 0}, {7, 8, 0}, {3, 4, 0}, {1, 2, 0}, {0, 1, 0} };
    for (int li = 0; li < 5; li++) {
        int s = small_[li].s, M = small_[li].M;
        gemm_small<<<G6 / 8, 256>>>(Htab + (size_t)(2 * s + 1) * HDIM, Wcat, Gh, M, G6, KCAT);
        pointwise<<<(M * HDIM + 255) / 256, 256>>>(s, M, Gh, 1, 0);
    }

    copyout<<<(N_OBJ * HDIM / 4) / 256, 256>>>((float*)d_out);
}

// round 11
// speedup vs baseline: 1.0968x; 1.0659x over previous
#include <cuda_runtime.h>
#include <cuda_bf16.h>
#include <math.h>
#include <stdint.h>

#define N_OBJ 2048
#define FDIM  2048
#define HDIM  1024
#define G6    6144          // 6*HDIM
#define NALL  7168          // 6*HDIM + HDIM (fused XG|PX width)
#define KCAT  2048          // 2*HDIM
#define NPAIR 96            // 3 terms * (2048/64) BK64 pairs

// plane strides (elements)
#define PS_F  ((size_t)N_OBJ * FDIM)
#define PS_WA ((size_t)NALL * FDIM)
#define PS_WC ((size_t)G6 * KCAT)
#define PS_H  ((size_t)(N_OBJ + 1) * HDIM)

// 3-term expansion: a0b0 + a0b1 + a1b0
#define TA_PACK 0x100u      // TA = {0,0,1}
#define TB_PACK 0x010u      // TB = {0,1,0}

// ---------------- scratch (static device globals; no allocation) -------------
__device__ float g_XGP[(size_t)N_OBJ * NALL];        // [XG | PX] fused
__device__ float g_Wcat[(size_t)G6 * KCAT];          // fp32 (tiny-M path)
__device__ float g_biaslr[G6];
__device__ float g_biasA[NALL];                      // b_iox | b_px
__device__ float g_C[(size_t)(N_OBJ + 1) * HDIM];
__device__ float g_H[(size_t)(N_OBJ + 1) * HDIM];
__device__ float g_Gh[(size_t)1536 * G6];            // split-K partial slabs

// bf16 split planes (2 planes each: hi, lo)
__device__ __nv_bfloat16 g_Fe [2 * PS_F];
__device__ __nv_bfloat16 g_WAe[2 * PS_WA];           // [w_iox; w_px] fused
__device__ __nv_bfloat16 g_Wce[2 * PS_WC];
__device__ __nv_bfloat16 g_He [2 * PS_H];

// ---------------- helpers ----------------------------------------------------
__device__ __forceinline__ uint32_t smem_to_u32(const void* p) {
    uint32_t a;
    asm("{ .reg .u64 t; cvta.to.shared.u64 t, %1; cvt.u32.u64 %0, t; }" : "=r"(a) : "l"(p));
    return a;
}
__device__ __forceinline__ void ldmx4(uint32_t* d, uint32_t addr) {
    asm volatile("ldmatrix.sync.aligned.m8n8.x4.shared.b16 {%0,%1,%2,%3}, [%4];"
                 : "=r"(d[0]), "=r"(d[1]), "=r"(d[2]), "=r"(d[3]) : "r"(addr));
}
__device__ __forceinline__ void mma_bf16(float* c, const uint32_t* a, const uint32_t* b) {
    asm volatile("mma.sync.aligned.m16n8k16.row.col.f32.bf16.bf16.f32 "
                 "{%0,%1,%2,%3}, {%4,%5,%6,%7}, {%8,%9}, {%0,%1,%2,%3};"
                 : "+f"(c[0]), "+f"(c[1]), "+f"(c[2]), "+f"(c[3])
                 : "r"(a[0]), "r"(a[1]), "r"(a[2]), "r"(a[3]), "r"(b[0]), "r"(b[1]));
}
__device__ __forceinline__ void cpasync16(uint32_t dst, const void* src) {
    asm volatile("cp.async.cg.shared.global [%0], [%1], 16;" :: "r"(dst), "l"(src));
}

// swizzle: 16B chunk x (0..3) within a 64B row r -> conflict-free for both
// cp.async stores and ldmatrix reads.
__device__ __forceinline__ uint32_t swz(int r, int x) {
    return (uint32_t)(r * 64 + ((x ^ ((r >> 1) & 3)) << 4));
}

// ---------------- bf16 double-split ------------------------------------------
__device__ __forceinline__ void bf16_split2(float x, __nv_bfloat16& t0, __nv_bfloat16& t1)
{
    t0 = __float2bfloat16(x);
    t1 = __float2bfloat16(x - __bfloat162float(t0));
}

// expand src fp32 [total] into 2 bf16 planes (hi, lo)
__global__ void expand_kernel(const float* __restrict__ src, __nv_bfloat16* __restrict__ dst,
                              size_t planeStride, int total)
{
    int i = blockIdx.x * 256 + threadIdx.x;
    if (i >= total) return;
    __nv_bfloat16 t0, t1;
    bf16_split2(src[i], t0, t1);
    dst[i] = t0;
    dst[planeStride + i] = t1;
}

// ---------------- prep: Wcat fp32, biases, sentinel rows ---------------------
__global__ void prep_kernel(const float* __restrict__ wl, const float* __restrict__ wr,
                            const float* __restrict__ bl, const float* __restrict__ br,
                            const float* __restrict__ bx, const float* __restrict__ bp)
{
    int idx = blockIdx.x * 256 + threadIdx.x;   // over G6*KCAT
    int j = idx >> 11;
    int k = idx & (KCAT - 1);
    float w = (k < HDIM) ? wl[(size_t)j * HDIM + k] : wr[(size_t)j * HDIM + (k - HDIM)];
    g_Wcat[idx] = w;
    if (idx < G6) { g_biaslr[idx] = bl[idx] + br[idx]; g_biasA[idx] = bx[idx]; }
    if (idx < HDIM) {
        g_biasA[G6 + idx] = bp[idx];
        size_t s = (size_t)N_OBJ * HDIM + idx;
        g_C[s] = 0.f; g_H[s] = 0.f;
        __nv_bfloat16 z = __float2bfloat16(0.f);
        g_He[s] = z; g_He[PS_H + s] = z;
    }
}

// ---------------- bf16 mma GEMM: C = sum_t A[TA(t)] @ B[TB(t)]^T (+bias) -----
// A, B: 2 bf16 planes, row stride 2048 within each plane.
// Stage = BK64 = two 32-wide sub-tiles, 3 stages; BN=128, BM in {128, 64}.
// BM=128: 2x4 warps (warp tile 64x32); BM=64: 1x8 warps (warp tile 64x16).
// Split-K: blockIdx.z = part p handles pairs [p*ppp, (p+1)*ppp), writes slab
// C + p*M*N. Deterministic.
template <int BM>
__global__ __launch_bounds__(256, 2) void gemm_bf(
    const __nv_bfloat16* __restrict__ A, size_t psA,
    const __nv_bfloat16* __restrict__ B, size_t psB,
    const float* __restrict__ bias, float* __restrict__ C, int M, int N, int ppp)
{
    constexpr int WCOLS = (BM == 128) ? 4 : 8;
    constexpr int WN = 128 / WCOLS;           // 32 / 16
    constexpr int NF = WN / 8;                // 4 / 2
    constexpr int ATB = BM * 64;              // A sub-tile bytes
    constexpr int SUB = ATB + 8192;           // A+B sub-tile
    constexpr int STAGE = 2 * SUB;            // BK64 stage bytes

    extern __shared__ char smem[];
    const uint32_t sb = smem_to_u32(smem);
    const int tid = threadIdx.x, lane = tid & 31, warp = tid >> 5;
    const int wr_ = warp / WCOLS, wc_ = warp % WCOLS;

    const int part = blockIdx.z;
    C += (size_t)part * M * N;
    const int p0 = part * ppp;

    // ---- L2-aware tile swizzle (within a part) ----
    const int tiles_n = gridDim.x, tiles_m = gridDim.y;
    int lid = blockIdx.y * tiles_n + blockIdx.x;
    const int GRP = 8;
    int per_group = GRP * tiles_m;
    int grp = lid / per_group, rem = lid - grp * per_group;
    int nt0 = grp * GRP;
    int gn = tiles_n - nt0; if (gn > GRP) gn = GRP;
    int nt = nt0 + rem % gn;
    int mt = rem / gn;
    const int row0 = mt * BM, col0 = nt * 128;

    // ldmatrix lane geometry
    const int lrow = ((lane >> 3) & 1) * 8 + (lane & 7);
    const int lcol = lane >> 4;

    // cp.async op coords
    const int r_op0 = tid >> 2,         ch0 = tid & 3;
    const int r_op1 = (tid + 256) >> 2, ch1 = tid & 3;

    float acc[4][NF][4];
#pragma unroll
    for (int a = 0; a < 4; a++)
#pragma unroll
        for (int b = 0; b < NF; b++)
#pragma unroll
            for (int t = 0; t < 4; t++) acc[a][b][t] = 0.f;

    // load one 32-wide chunk c into sub-slot (A @ off, B @ off+ATB)
    auto load_sub = [&](int c, uint32_t off) {
        int t = c >> 6;
        size_t pa = (size_t)((TA_PACK >> (4 * t)) & 0xF) * psA;
        size_t pb = (size_t)((TB_PACK >> (4 * t)) & 0xF) * psB;
        const __nv_bfloat16* Ab = A + pa + (size_t)(c & 63) * 32;
        const __nv_bfloat16* Bb = B + pb + (size_t)(c & 63) * 32;
        uint32_t sA = sb + off, sBm = sA + ATB;
        cpasync16(sA + swz(r_op0, ch0), Ab + (size_t)(row0 + r_op0) * 2048 + ch0 * 8);
        if (BM == 128)
            cpasync16(sA + swz(r_op1, ch1), Ab + (size_t)(row0 + r_op1) * 2048 + ch1 * 8);
        cpasync16(sBm + swz(r_op0, ch0), Bb + (size_t)(col0 + r_op0) * 2048 + ch0 * 8);
        cpasync16(sBm + swz(r_op1, ch1), Bb + (size_t)(col0 + r_op1) * 2048 + ch1 * 8);
    };
    auto load_pair = [&](int p, int st) {
        load_sub(2 * p,     (uint32_t)(st * STAGE));
        load_sub(2 * p + 1, (uint32_t)(st * STAGE + SUB));
        asm volatile("cp.async.commit_group;" ::: "memory");
    };
    // fragment load for k16 step kk (0..3) of stage st
    auto ldfrag = [&](int st, int kk, uint32_t af[4][4], uint32_t bq[2][4]) {
        uint32_t sA = sb + st * STAGE + (kk >> 1) * SUB;
        uint32_t sBm = sA + ATB;
        int kl = (kk & 1) * 2 + lcol;
#pragma unroll
        for (int mf = 0; mf < 4; mf++) {
            int r = wr_ * 64 + mf * 16 + lrow;
            ldmx4(af[mf], sA + swz(r, kl));
        }
#pragma unroll
        for (int bh = 0; bh < WN / 16; bh++) {
            int r = wc_ * WN + bh * 16 + lrow;
            ldmx4(bq[bh], sBm + swz(r, kl));
        }
    };

    load_pair(p0, 0); load_pair(p0 + 1, 1);

    uint32_t fA[2][4][4], fB[2][2][4];

    for (int i = 0; i < ppp; i++) {
        int st = i % 3;
        if (i + 2 < ppp) {
            asm volatile("cp.async.wait_group 1;" ::: "memory");
        } else {
            asm volatile("cp.async.wait_group 0;" ::: "memory");   // tail drain
        }
        __syncthreads();
        if (i + 2 < ppp) load_pair(p0 + i + 2, (i + 2) % 3);

        ldfrag(st, 0, fA[0], fB[0]);
#pragma unroll
        for (int kk = 0; kk < 4; kk++) {
            if (kk < 3) ldfrag(st, kk + 1, fA[(kk + 1) & 1], fB[(kk + 1) & 1]);
            uint32_t (*af)[4] = fA[kk & 1];
            uint32_t (*bq)[4] = fB[kk & 1];
#pragma unroll
            for (int mf = 0; mf < 4; mf++)
#pragma unroll
                for (int nf = 0; nf < NF; nf++) {
                    uint32_t b2[2] = { bq[nf >> 1][nf & 1], bq[nf >> 1][2 + (nf & 1)] };
                    mma_bf16(acc[mf][nf], af[mf], b2);
                }
        }
    }

    // ---- epilogue ----
#pragma unroll
    for (int mf = 0; mf < 4; mf++) {
#pragma unroll
        for (int nf = 0; nf < NF; nf++) {
            int r  = row0 + wr_ * 64 + mf * 16 + (lane >> 2);
            int cb = col0 + wc_ * WN + nf * 8 + (lane & 3) * 2;
            float b0 = bias ? bias[cb] : 0.f;
            float b1 = bias ? bias[cb + 1] : 0.f;
            if (r < M) {
                C[(size_t)r * N + cb]     = acc[mf][nf][0] + b0;
                C[(size_t)r * N + cb + 1] = acc[mf][nf][1] + b1;
            }
            if (r + 8 < M) {
                C[(size_t)(r + 8) * N + cb]     = acc[mf][nf][2] + b0;
                C[(size_t)(r + 8) * N + cb + 1] = acc[mf][nf][3] + b1;
            }
        }
    }
}

// ---------------- tiny-M GEMM (M<=16): one warp per output column n ---------
__global__ void gemm_small(const float* __restrict__ A, const float* __restrict__ B,
                           float* __restrict__ C, int M, int N, int K)
{
    int warp = threadIdx.x >> 5, lane = threadIdx.x & 31;
    int n = blockIdx.x * 8 + warp;
    if (n >= N) return;
    float acc[16];
#pragma unroll
    for (int m = 0; m < 16; m++) acc[m] = 0.f;
    const float* Brow = B + (size_t)n * K;
    for (int k = lane * 4; k < K; k += 128) {
        float4 bv = *(const float4*)(Brow + k);
#pragma unroll
        for (int m = 0; m < 16; m++) {
            if (m < M) {
                float4 av = *(const float4*)(A + (size_t)m * K + k);
                acc[m] += av.x * bv.x + av.y * bv.y + av.z * bv.z + av.w * bv.w;
            }
        }
    }
#pragma unroll
    for (int m = 0; m < 16; m++) {
        if (m < M) {
            float v = acc[m];
#pragma unroll
            for (int off = 16; off; off >>= 1) v += __shfl_xor_sync(~0u, v, off);
            if (lane == 0) C[(size_t)m * N + n] = v;
        }
    }
}

// ---------------- pointwise LSTM cell for one wavefront ----------------------
__device__ __forceinline__ float sigm(float x) { return 1.f / (1.f + expf(-x)); }

__global__ void pointwise(int s, int M, const float* __restrict__ Gh,
                          int nparts, int pstride, float* __restrict__ out)
{
    int idx = blockIdx.x * blockDim.x + threadIdx.x;
    if (idx >= M * HDIM) return;
    int m = idx >> 10;
    int j = idx & (HDIM - 1);
    int n = s + m;

    const float* xg = g_XGP + (size_t)n * NALL;
    float g[6];
#pragma unroll
    for (int t = 0; t < 6; t++) {
        int o = t * HDIM + j;
        float v = xg[o] + g_biaslr[o];
        for (int p = 0; p < nparts; p++)
            v += Gh[(size_t)p * pstride + (size_t)m * G6 + o];
        g[t] = v;
    }
    float ig = sigm(g[0]), og = sigm(g[1]);
    float fl = sigm(g[2]), fr = sigm(g[3]);
    float u  = tanhf(g[4]), rr = sigm(g[5]);

    int l = 2 * n + 1; if (l > N_OBJ) l = N_OBJ;
    int r = 2 * n + 2; if (r > N_OBJ) r = N_OBJ;

    float c = ig * u + fl * g_C[(size_t)l * HDIM + j] + fr * g_C[(size_t)r * HDIM + j];
    float h = og * tanhf(c);
    float hf = rr * h + (1.f - rr) * xg[G6 + j];     // px fused at cols [6144,7168)

    size_t o = (size_t)n * HDIM + j;
    g_C[o] = c;
    g_H[o] = hf;
    out[o] = hf;
    __nv_bfloat16 t0, t1;
    bf16_split2(hf, t0, t1);
    g_He[o] = t0; g_He[PS_H + o] = t1;
}

// ---------------- launcher ---------------------------------------------------
extern "C" void kernel_launch(void* const* d_in, const int* in_sizes, int n_in,
                              void* d_out, int out_size)
{
    const float* features = (const float*)d_in[0];
    const float* w_iox    = (const float*)d_in[1];
    const float* b_iox    = (const float*)d_in[2];
    const float* w_l      = (const float*)d_in[3];
    const float* b_l      = (const float*)d_in[4];
    const float* w_r      = (const float*)d_in[5];
    const float* b_r      = (const float*)d_in[6];
    const float* w_px     = (const float*)d_in[7];
    const float* b_px     = (const float*)d_in[8];
    float* out = (float*)d_out;

    float *XGP, *Wcat, *Gh, *Htab, *biasA;
    __nv_bfloat16 *Fe, *WAe, *Wce, *He;
    cudaGetSymbolAddress((void**)&XGP,   g_XGP);
    cudaGetSymbolAddress((void**)&Wcat,  g_Wcat);
    cudaGetSymbolAddress((void**)&Gh,    g_Gh);
    cudaGetSymbolAddress((void**)&Htab,  g_H);
    cudaGetSymbolAddress((void**)&biasA, g_biasA);
    cudaGetSymbolAddress((void**)&Fe,    g_Fe);
    cudaGetSymbolAddress((void**)&WAe,   g_WAe);
    cudaGetSymbolAddress((void**)&Wce,   g_Wce);
    cudaGetSymbolAddress((void**)&He,    g_He);

    const int SMEM_128 = 3 * 32768;
    const int SMEM_64  = 3 * 24576;
    cudaFuncSetAttribute(gemm_bf<128>, cudaFuncAttributeMaxDynamicSharedMemorySize, SMEM_128);
    cudaFuncSetAttribute(gemm_bf<64>,  cudaFuncAttributeMaxDynamicSharedMemorySize, SMEM_64);

    // prep + operand 2-plane expansion
    prep_kernel<<<(G6 * KCAT) / 256, 256>>>(w_l, w_r, b_l, b_r, b_iox, b_px);
    expand_kernel<<<(int)((PS_F + 255) / 256), 256>>>(features, Fe, PS_F, (int)PS_F);
    expand_kernel<<<(int)(((size_t)G6 * FDIM + 255) / 256), 256>>>(
        w_iox, WAe, PS_WA, (int)((size_t)G6 * FDIM));
    expand_kernel<<<(int)(((size_t)HDIM * FDIM + 255) / 256), 256>>>(
        w_px, WAe + (size_t)G6 * FDIM, PS_WA, (int)((size_t)HDIM * FDIM));
    expand_kernel<<<(int)((PS_WC + 255) / 256), 256>>>(Wcat, Wce, PS_WC, (int)PS_WC);

    // phase A: fused [XG | PX] GEMM, N = 7168
    gemm_bf<128><<<dim3(NALL / 128, N_OBJ / 128, 1), 256, SMEM_128>>>(
        Fe, PS_F, WAe, PS_WA, biasA, XGP, N_OBJ, NALL, NPAIR);

    // leaves
    pointwise<<<(1024 * HDIM + 255) / 256, 256>>>(1024, 1024, nullptr, 0, 0, out);

    // node 1023 (single, fp32 path; children rows 2047 + sentinel 2048)
    gemm_small<<<G6 / 8, 256>>>(Htab + (size_t)2047 * HDIM, Wcat, Gh, 1, G6, KCAT);
    pointwise<<<(1 * HDIM + 255) / 256, 256>>>(1023, 1, Gh, 1, 0, out);

    // big internal wavefronts with deterministic split-K (wave-packed KS)
    struct Lv { int s, M, KS, BM; };
    const Lv big[5] = { {511, 512, 3, 128}, {255, 256, 3, 128}, {127, 128, 6, 128},
                        {63, 64, 6, 64}, {31, 32, 6, 64} };
    for (int li = 0; li < 5; li++) {
        int s = big[li].s, M = big[li].M, KS = big[li].KS;
        const __nv_bfloat16* Ab = He + (size_t)(2 * s + 1) * HDIM;
        if (big[li].BM == 128) {
            int Mtiles = (M + 127) / 128;
            gemm_bf<128><<<dim3(G6 / 128, Mtiles, KS), 256, SMEM_128>>>(
                Ab, PS_H, Wce, PS_WC, nullptr, Gh, M, G6, NPAIR / KS);
        } else {
            gemm_bf<64><<<dim3(G6 / 128, 1, KS), 256, SMEM_64>>>(
                Ab, PS_H, Wce, PS_WC, nullptr, Gh, M, G6, NPAIR / KS);
        }
        pointwise<<<(M * HDIM + 255) / 256, 256>>>(s, M, Gh, KS, M * G6, out);
    }

    // tiny wavefronts (fp32 warp-dot)
    const Lv small_[5] = { {15, 16, 0, 0}, {7, 8, 0, 0}, {3, 4, 0, 0},
                           {1, 2, 0, 0}, {0, 1, 0, 0} };
    for (int li = 0; li < 5; li++) {
        int s = small_[li].s, M = small_[li].M;
        gemm_small<<<G6 / 8, 256>>>(Htab + (size_t)(2 * s + 1) * HDIM, Wcat, Gh, M, G6, KCAT);
        pointwise<<<(M * HDIM + 255) / 256, 256>>>(s, M, Gh, 1, 0, out);
    }
}

// round 12
// speedup vs baseline: 1.3334x; 1.2157x over previous
#include <cuda_runtime.h>
#include <cuda_fp16.h>
#include <math.h>
#include <stdint.h>

#define N_OBJ 2048
#define FDIM  2048
#define HDIM  1024
#define G6    6144          // 6*HDIM
#define NALL  7168          // 6*HDIM + HDIM (fused XG|PX width)
#define KCAT  2048          // 2*HDIM
#define NPAIR 64            // 2 terms * (2048/64) BK64 pairs

// plane strides (elements)
#define PS_F  ((size_t)N_OBJ * FDIM)
#define PS_WA ((size_t)NALL * FDIM)
#define PS_WC ((size_t)G6 * KCAT)
#define PS_H  ((size_t)(N_OBJ + 1) * HDIM)

// ---------------- scratch (static device globals; no allocation) -------------
__device__ float g_XGP[(size_t)N_OBJ * NALL];        // [XG | PX] fused
__device__ float g_Wcat[(size_t)G6 * KCAT];          // fp32 (tiny-M path)
__device__ float g_biaslr[G6];
__device__ float g_biasA[NALL];                      // b_iox | b_px
__device__ float g_C[(size_t)(N_OBJ + 1) * HDIM];
__device__ float g_H[(size_t)(N_OBJ + 1) * HDIM];
__device__ float g_Gh[(size_t)2048 * G6];            // split-K partial slabs

// fp16 operand planes: A-side single plane, B-side hi+lo planes
__device__ __half g_Fe [PS_F];                       // features (1 plane)
__device__ __half g_WAe[2 * PS_WA];                  // [w_iox; w_px] hi+lo
__device__ __half g_Wce[2 * PS_WC];                  // Wcat hi+lo
__device__ __half g_He [PS_H];                       // hidden (1 plane)

// ---------------- helpers ----------------------------------------------------
__device__ __forceinline__ uint32_t smem_to_u32(const void* p) {
    uint32_t a;
    asm("{ .reg .u64 t; cvta.to.shared.u64 t, %1; cvt.u32.u64 %0, t; }" : "=r"(a) : "l"(p));
    return a;
}
__device__ __forceinline__ void ldmx4(uint32_t* d, uint32_t addr) {
    asm volatile("ldmatrix.sync.aligned.m8n8.x4.shared.b16 {%0,%1,%2,%3}, [%4];"
                 : "=r"(d[0]), "=r"(d[1]), "=r"(d[2]), "=r"(d[3]) : "r"(addr));
}
__device__ __forceinline__ void mma_f16(float* c, const uint32_t* a, const uint32_t* b) {
    asm volatile("mma.sync.aligned.m16n8k16.row.col.f32.f16.f16.f32 "
                 "{%0,%1,%2,%3}, {%4,%5,%6,%7}, {%8,%9}, {%0,%1,%2,%3};"
                 : "+f"(c[0]), "+f"(c[1]), "+f"(c[2]), "+f"(c[3])
                 : "r"(a[0]), "r"(a[1]), "r"(a[2]), "r"(a[3]), "r"(b[0]), "r"(b[1]));
}
__device__ __forceinline__ void cpasync16(uint32_t dst, const void* src) {
    asm volatile("cp.async.cg.shared.global [%0], [%1], 16;" :: "r"(dst), "l"(src));
}

// swizzle: 16B chunk x (0..3) within a 64B row r -> conflict-free for both
// cp.async stores and ldmatrix reads.
__device__ __forceinline__ uint32_t swz(int r, int x) {
    return (uint32_t)(r * 64 + ((x ^ ((r >> 1) & 3)) << 4));
}

// ---------------- fp16 splits -------------------------------------------------
__device__ __forceinline__ void half_split2(float x, __half& t0, __half& t1)
{
    t0 = __float2half_rn(x);
    t1 = __float2half_rn(x - __half2float(t0));
}

// expand src fp32 into ONE fp16 plane
__global__ void expand1_kernel(const float* __restrict__ src, __half* __restrict__ dst,
                               int total)
{
    int i = blockIdx.x * 256 + threadIdx.x;
    if (i < total) dst[i] = __float2half_rn(src[i]);
}

// expand src fp32 into TWO fp16 planes (hi, lo)
__global__ void expand2_kernel(const float* __restrict__ src, __half* __restrict__ dst,
                               size_t planeStride, int total)
{
    int i = blockIdx.x * 256 + threadIdx.x;
    if (i >= total) return;
    __half t0, t1;
    half_split2(src[i], t0, t1);
    dst[i] = t0;
    dst[planeStride + i] = t1;
}

// ---------------- prep: Wcat fp32, biases, sentinel rows ---------------------
__global__ void prep_kernel(const float* __restrict__ wl, const float* __restrict__ wr,
                            const float* __restrict__ bl, const float* __restrict__ br,
                            const float* __restrict__ bx, const float* __restrict__ bp)
{
    int idx = blockIdx.x * 256 + threadIdx.x;   // over G6*KCAT
    int j = idx >> 11;
    int k = idx & (KCAT - 1);
    float w = (k < HDIM) ? wl[(size_t)j * HDIM + k] : wr[(size_t)j * HDIM + (k - HDIM)];
    g_Wcat[idx] = w;
    if (idx < G6) { g_biaslr[idx] = bl[idx] + br[idx]; g_biasA[idx] = bx[idx]; }
    if (idx < HDIM) {
        g_biasA[G6 + idx] = bp[idx];
        size_t s = (size_t)N_OBJ * HDIM + idx;
        g_C[s] = 0.f; g_H[s] = 0.f;
        g_He[s] = __float2half_rn(0.f);
    }
}

// ---------------- fp16 mma GEMM: C = A @ (B0+B1)^T (+bias) -------------------
// A: 1 fp16 plane; B: 2 fp16 planes. Row stride 2048 within each plane.
// Chunk c (0..127): term t = c>>6 selects B plane; A plane always 0.
// Stage = BK64 = two 32-wide sub-tiles, 3 stages; BN=128, BM in {128, 64}.
// Split-K: blockIdx.z = part p handles pairs [p*ppp, (p+1)*ppp), writes slab
// C + p*M*N. Deterministic.
template <int BM>
__global__ __launch_bounds__(256, 2) void gemm_hf(
    const __half* __restrict__ A,
    const __half* __restrict__ B, size_t psB,
    const float* __restrict__ bias, float* __restrict__ C, int M, int N, int ppp)
{
    constexpr int WCOLS = (BM == 128) ? 4 : 8;
    constexpr int WN = 128 / WCOLS;           // 32 / 16
    constexpr int NF = WN / 8;                // 4 / 2
    constexpr int ATB = BM * 64;              // A sub-tile bytes
    constexpr int SUB = ATB + 8192;           // A+B sub-tile
    constexpr int STAGE = 2 * SUB;            // BK64 stage bytes

    extern __shared__ char smem[];
    const uint32_t sb = smem_to_u32(smem);
    const int tid = threadIdx.x, lane = tid & 31, warp = tid >> 5;
    const int wr_ = warp / WCOLS, wc_ = warp % WCOLS;

    const int part = blockIdx.z;
    C += (size_t)part * M * N;
    const int p0 = part * ppp;

    // ---- L2-aware tile swizzle (within a part) ----
    const int tiles_n = gridDim.x, tiles_m = gridDim.y;
    int lid = blockIdx.y * tiles_n + blockIdx.x;
    const int GRP = 8;
    int per_group = GRP * tiles_m;
    int grp = lid / per_group, rem = lid - grp * per_group;
    int nt0 = grp * GRP;
    int gn = tiles_n - nt0; if (gn > GRP) gn = GRP;
    int nt = nt0 + rem % gn;
    int mt = rem / gn;
    const int row0 = mt * BM, col0 = nt * 128;

    // ldmatrix lane geometry
    const int lrow = ((lane >> 3) & 1) * 8 + (lane & 7);
    const int lcol = lane >> 4;

    // cp.async op coords
    const int r_op0 = tid >> 2,         ch0 = tid & 3;
    const int r_op1 = (tid + 256) >> 2, ch1 = tid & 3;

    float acc[4][NF][4];
#pragma unroll
    for (int a = 0; a < 4; a++)
#pragma unroll
        for (int b = 0; b < NF; b++)
#pragma unroll
            for (int t = 0; t < 4; t++) acc[a][b][t] = 0.f;

    // load one 32-wide chunk c into sub-slot (A @ off, B @ off+ATB)
    auto load_sub = [&](int c, uint32_t off) {
        int t = c >> 6;                              // B plane select
        const __half* Ab = A + (size_t)(c & 63) * 32;
        const __half* Bb = B + (size_t)t * psB + (size_t)(c & 63) * 32;
        uint32_t sA = sb + off, sBm = sA + ATB;
        cpasync16(sA + swz(r_op0, ch0), Ab + (size_t)(row0 + r_op0) * 2048 + ch0 * 8);
        if (BM == 128)
            cpasync16(sA + swz(r_op1, ch1), Ab + (size_t)(row0 + r_op1) * 2048 + ch1 * 8);
        cpasync16(sBm + swz(r_op0, ch0), Bb + (size_t)(col0 + r_op0) * 2048 + ch0 * 8);
        cpasync16(sBm + swz(r_op1, ch1), Bb + (size_t)(col0 + r_op1) * 2048 + ch1 * 8);
    };
    auto load_pair = [&](int p, int st) {
        load_sub(2 * p,     (uint32_t)(st * STAGE));
        load_sub(2 * p + 1, (uint32_t)(st * STAGE + SUB));
        asm volatile("cp.async.commit_group;" ::: "memory");
    };
    // fragment load for k16 step kk (0..3) of stage st
    auto ldfrag = [&](int st, int kk, uint32_t af[4][4], uint32_t bq[2][4]) {
        uint32_t sA = sb + st * STAGE + (kk >> 1) * SUB;
        uint32_t sBm = sA + ATB;
        int kl = (kk & 1) * 2 + lcol;
#pragma unroll
        for (int mf = 0; mf < 4; mf++) {
            int r = wr_ * 64 + mf * 16 + lrow;
            ldmx4(af[mf], sA + swz(r, kl));
        }
#pragma unroll
        for (int bh = 0; bh < WN / 16; bh++) {
            int r = wc_ * WN + bh * 16 + lrow;
            ldmx4(bq[bh], sBm + swz(r, kl));
        }
    };

    load_pair(p0, 0); load_pair(p0 + 1, 1);

    uint32_t fA[2][4][4], fB[2][2][4];

    for (int i = 0; i < ppp; i++) {
        int st = i % 3;
        if (i + 2 < ppp) {
            asm volatile("cp.async.wait_group 1;" ::: "memory");
        } else {
            asm volatile("cp.async.wait_group 0;" ::: "memory");   // tail drain
        }
        __syncthreads();
        if (i + 2 < ppp) load_pair(p0 + i + 2, (i + 2) % 3);

        ldfrag(st, 0, fA[0], fB[0]);
#pragma unroll
        for (int kk = 0; kk < 4; kk++) {
            if (kk < 3) ldfrag(st, kk + 1, fA[(kk + 1) & 1], fB[(kk + 1) & 1]);
            uint32_t (*af)[4] = fA[kk & 1];
            uint32_t (*bq)[4] = fB[kk & 1];
#pragma unroll
            for (int mf = 0; mf < 4; mf++)
#pragma unroll
                for (int nf = 0; nf < NF; nf++) {
                    uint32_t b2[2] = { bq[nf >> 1][nf & 1], bq[nf >> 1][2 + (nf & 1)] };
                    mma_f16(acc[mf][nf], af[mf], b2);
                }
        }
    }

    // ---- epilogue ----
#pragma unroll
    for (int mf = 0; mf < 4; mf++) {
#pragma unroll
        for (int nf = 0; nf < NF; nf++) {
            int r  = row0 + wr_ * 64 + mf * 16 + (lane >> 2);
            int cb = col0 + wc_ * WN + nf * 8 + (lane & 3) * 2;
            float b0 = bias ? bias[cb] : 0.f;
            float b1 = bias ? bias[cb + 1] : 0.f;
            if (r < M) {
                C[(size_t)r * N + cb]     = acc[mf][nf][0] + b0;
                C[(size_t)r * N + cb + 1] = acc[mf][nf][1] + b1;
            }
            if (r + 8 < M) {
                C[(size_t)(r + 8) * N + cb]     = acc[mf][nf][2] + b0;
                C[(size_t)(r + 8) * N + cb + 1] = acc[mf][nf][3] + b1;
            }
        }
    }
}

// ---------------- tiny-M GEMM (M<=16): one warp per output column n ---------
__global__ void gemm_small(const float* __restrict__ A, const float* __restrict__ B,
                           float* __restrict__ C, int M, int N, int K)
{
    int warp = threadIdx.x >> 5, lane = threadIdx.x & 31;
    int n = blockIdx.x * 8 + warp;
    if (n >= N) return;
    float acc[16];
#pragma unroll
    for (int m = 0; m < 16; m++) acc[m] = 0.f;
    const float* Brow = B + (size_t)n * K;
    for (int k = lane * 4; k < K; k += 128) {
        float4 bv = *(const float4*)(Brow + k);
#pragma unroll
        for (int m = 0; m < 16; m++) {
            if (m < M) {
                float4 av = *(const float4*)(A + (size_t)m * K + k);
                acc[m] += av.x * bv.x + av.y * bv.y + av.z * bv.z + av.w * bv.w;
            }
        }
    }
#pragma unroll
    for (int m = 0; m < 16; m++) {
        if (m < M) {
            float v = acc[m];
#pragma unroll
            for (int off = 16; off; off >>= 1) v += __shfl_xor_sync(~0u, v, off);
            if (lane == 0) C[(size_t)m * N + n] = v;
        }
    }
}

// ---------------- pointwise LSTM cell for one wavefront ----------------------
__device__ __forceinline__ float sigm(float x) { return 1.f / (1.f + expf(-x)); }

__global__ void pointwise(int s, int M, const float* __restrict__ Gh,
                          int nparts, int pstride, float* __restrict__ out)
{
    int idx = blockIdx.x * blockDim.x + threadIdx.x;
    if (idx >= M * HDIM) return;
    int m = idx >> 10;
    int j = idx & (HDIM - 1);
    int n = s + m;

    const float* xg = g_XGP + (size_t)n * NALL;
    float g[6];
#pragma unroll
    for (int t = 0; t < 6; t++) {
        int o = t * HDIM + j;
        float v = xg[o] + g_biaslr[o];
        for (int p = 0; p < nparts; p++)
            v += Gh[(size_t)p * pstride + (size_t)m * G6 + o];
        g[t] = v;
    }
    float ig = sigm(g[0]), og = sigm(g[1]);
    float fl = sigm(g[2]), fr = sigm(g[3]);
    float u  = tanhf(g[4]), rr = sigm(g[5]);

    int l = 2 * n + 1; if (l > N_OBJ) l = N_OBJ;
    int r = 2 * n + 2; if (r > N_OBJ) r = N_OBJ;

    float c = ig * u + fl * g_C[(size_t)l * HDIM + j] + fr * g_C[(size_t)r * HDIM + j];
    float h = og * tanhf(c);
    float hf = rr * h + (1.f - rr) * xg[G6 + j];     // px fused at cols [6144,7168)

    size_t o = (size_t)n * HDIM + j;
    g_C[o] = c;
    g_H[o] = hf;
    out[o] = hf;
    g_He[o] = __float2half_rn(hf);
}

// ---------------- launcher ---------------------------------------------------
extern "C" void kernel_launch(void* const* d_in, const int* in_sizes, int n_in,
                              void* d_out, int out_size)
{
    const float* features = (const float*)d_in[0];
    const float* w_iox    = (const float*)d_in[1];
    const float* b_iox    = (const float*)d_in[2];
    const float* w_l      = (const float*)d_in[3];
    const float* b_l      = (const float*)d_in[4];
    const float* w_r      = (const float*)d_in[5];
    const float* b_r      = (const float*)d_in[6];
    const float* w_px     = (const float*)d_in[7];
    const float* b_px     = (const float*)d_in[8];
    float* out = (float*)d_out;

    float *XGP, *Wcat, *Gh, *Htab, *biasA;
    __half *Fe, *WAe, *Wce, *He;
    cudaGetSymbolAddress((void**)&XGP,   g_XGP);
    cudaGetSymbolAddress((void**)&Wcat,  g_Wcat);
    cudaGetSymbolAddress((void**)&Gh,    g_Gh);
    cudaGetSymbolAddress((void**)&Htab,  g_H);
    cudaGetSymbolAddress((void**)&biasA, g_biasA);
    cudaGetSymbolAddress((void**)&Fe,    g_Fe);
    cudaGetSymbolAddress((void**)&WAe,   g_WAe);
    cudaGetSymbolAddress((void**)&Wce,   g_Wce);
    cudaGetSymbolAddress((void**)&He,    g_He);

    const int SMEM_128 = 3 * 32768;
    const int SMEM_64  = 3 * 24576;
    cudaFuncSetAttribute(gemm_hf<128>, cudaFuncAttributeMaxDynamicSharedMemorySize, SMEM_128);
    cudaFuncSetAttribute(gemm_hf<64>,  cudaFuncAttributeMaxDynamicSharedMemorySize, SMEM_64);

    // prep + operand expansion (A: 1 plane; weights: 2 planes)
    prep_kernel<<<(G6 * KCAT) / 256, 256>>>(w_l, w_r, b_l, b_r, b_iox, b_px);
    expand1_kernel<<<(int)((PS_F + 255) / 256), 256>>>(features, Fe, (int)PS_F);
    expand2_kernel<<<(int)(((size_t)G6 * FDIM + 255) / 256), 256>>>(
        w_iox, WAe, PS_WA, (int)((size_t)G6 * FDIM));
    expand2_kernel<<<(int)(((size_t)HDIM * FDIM + 255) / 256), 256>>>(
        w_px, WAe + (size_t)G6 * FDIM, PS_WA, (int)((size_t)HDIM * FDIM));
    expand2_kernel<<<(int)((PS_WC + 255) / 256), 256>>>(Wcat, Wce, PS_WC, (int)PS_WC);

    // phase A: fused [XG | PX] GEMM, N = 7168
    gemm_hf<128><<<dim3(NALL / 128, N_OBJ / 128, 1), 256, SMEM_128>>>(
        Fe, WAe, PS_WA, biasA, XGP, N_OBJ, NALL, NPAIR);

    // leaves
    pointwise<<<(1024 * HDIM + 255) / 256, 256>>>(1024, 1024, nullptr, 0, 0, out);

    // node 1023 (single, fp32 path; children rows 2047 + sentinel 2048)
    gemm_small<<<G6 / 8, 256>>>(Htab + (size_t)2047 * HDIM, Wcat, Gh, 1, G6, KCAT);
    pointwise<<<(1 * HDIM + 255) / 256, 256>>>(1023, 1, Gh, 1, 0, out);

    // big internal wavefronts with deterministic split-K (wave-packed KS)
    struct Lv { int s, M, KS, BM; };
    const Lv big[5] = { {511, 512, 4, 128}, {255, 256, 8, 128}, {127, 128, 8, 128},
                        {63, 64, 8, 64}, {31, 32, 8, 64} };
    for (int li = 0; li < 5; li++) {
        int s = big[li].s, M = big[li].M, KS = big[li].KS;
        const __half* Ab = He + (size_t)(2 * s + 1) * HDIM;
        if (big[li].BM == 128) {
            int Mtiles = (M + 127) / 128;
            gemm_hf<128><<<dim3(G6 / 128, Mtiles, KS), 256, SMEM_128>>>(
                Ab, Wce, PS_WC, nullptr, Gh, M, G6, NPAIR / KS);
        } else {
            gemm_hf<64><<<dim3(G6 / 128, 1, KS), 256, SMEM_64>>>(
                Ab, Wce, PS_WC, nullptr, Gh, M, G6, NPAIR / KS);
        }
        pointwise<<<(M * HDIM + 255) / 256, 256>>>(s, M, Gh, KS, M * G6, out);
    }

    // tiny wavefronts (fp32 warp-dot)
    const Lv small_[5] = { {15, 16, 0, 0}, {7, 8, 0, 0}, {3, 4, 0, 0},
                           {1, 2, 0, 0}, {0, 1, 0, 0} };
    for (int li = 0; li < 5; li++) {
        int s = small_[li].s, M = small_[li].M;
        gemm_small<<<G6 / 8, 256>>>(Htab + (size_t)(2 * s + 1) * HDIM, Wcat, Gh, M, G6, KCAT);
        pointwise<<<(M * HDIM + 255) / 256, 256>>>(s, M, Gh, 1, 0, out);
    }
}

// round 14
// speedup vs baseline: 2.0133x; 1.5099x over previous
#include <cuda_runtime.h>
#include <cuda_fp16.h>
#include <math.h>
#include <stdint.h>

#define N_OBJ 2048
#define FDIM  2048
#define HDIM  1024
#define G6    6144          // 6*HDIM
#define NALL  7168          // 6*HDIM + HDIM (fused XG|PX width)
#define KCAT  2048          // 2*HDIM
#define NPAIR 32            // (2048/64) BK64 pairs, single term

// plane strides (elements)
#define PS_F  ((size_t)N_OBJ * FDIM)
#define PS_WA ((size_t)NALL * FDIM)
#define PS_WC ((size_t)G6 * KCAT)
#define PS_H  ((size_t)(N_OBJ + 1) * HDIM)

// ---------------- scratch (static device globals; no allocation) -------------
__device__ float g_XGP[(size_t)N_OBJ * NALL];        // [XG | PX] fused
__device__ float g_biaslr[G6];
__device__ float g_biasA[NALL];                      // b_iox | b_px
__device__ float g_C[(size_t)(N_OBJ + 1) * HDIM];
__device__ float g_H[(size_t)(N_OBJ + 1) * HDIM];
__device__ float g_Gh[(size_t)2048 * G6];            // split-K partial slabs

// fp16 operand planes (single plane each side)
__device__ __half g_Fe [PS_F];                       // features
__device__ __half g_WAe[PS_WA];                      // [w_iox; w_px]
__device__ __half g_Wce[PS_WC];                      // [Wl | Wr]
__device__ __half g_He [PS_H];                       // hidden

// ---------------- helpers ----------------------------------------------------
__device__ __forceinline__ uint32_t smem_to_u32(const void* p) {
    uint32_t a;
    asm("{ .reg .u64 t; cvta.to.shared.u64 t, %1; cvt.u32.u64 %0, t; }" : "=r"(a) : "l"(p));
    return a;
}
__device__ __forceinline__ void ldmx4(uint32_t* d, uint32_t addr) {
    asm volatile("ldmatrix.sync.aligned.m8n8.x4.shared.b16 {%0,%1,%2,%3}, [%4];"
                 : "=r"(d[0]), "=r"(d[1]), "=r"(d[2]), "=r"(d[3]) : "r"(addr));
}
__device__ __forceinline__ void mma_f16(float* c, const uint32_t* a, const uint32_t* b) {
    asm volatile("mma.sync.aligned.m16n8k16.row.col.f32.f16.f16.f32 "
                 "{%0,%1,%2,%3}, {%4,%5,%6,%7}, {%8,%9}, {%0,%1,%2,%3};"
                 : "+f"(c[0]), "+f"(c[1]), "+f"(c[2]), "+f"(c[3])
                 : "r"(a[0]), "r"(a[1]), "r"(a[2]), "r"(a[3]), "r"(b[0]), "r"(b[1]));
}
__device__ __forceinline__ void cpasync16(uint32_t dst, const void* src) {
    asm volatile("cp.async.cg.shared.global [%0], [%1], 16;" :: "r"(dst), "l"(src));
}

// swizzle: 16B chunk x (0..3) within a 64B row r -> conflict-free for both
// cp.async stores and ldmatrix reads.
__device__ __forceinline__ uint32_t swz(int r, int x) {
    return (uint32_t)(r * 64 + ((x ^ ((r >> 1) & 3)) << 4));
}

// ---------------- expansion kernels ------------------------------------------
__global__ void expand1_kernel(const float* __restrict__ src, __half* __restrict__ dst,
                               int total)
{
    int i = blockIdx.x * 256 + threadIdx.x;
    if (i < total) dst[i] = __float2half_rn(src[i]);
}

// build fp16 [Wl | Wr] concat directly from inputs
__global__ void expand_wc_kernel(const float* __restrict__ wl, const float* __restrict__ wr)
{
    int idx = blockIdx.x * 256 + threadIdx.x;   // over G6*KCAT
    int j = idx >> 11;
    int k = idx & (KCAT - 1);
    float w = (k < HDIM) ? wl[(size_t)j * HDIM + k] : wr[(size_t)j * HDIM + (k - HDIM)];
    g_Wce[idx] = __float2half_rn(w);
}

// ---------------- prep: biases + sentinel rows -------------------------------
__global__ void prep_kernel(const float* __restrict__ bl, const float* __restrict__ br,
                            const float* __restrict__ bx, const float* __restrict__ bp)
{
    int idx = blockIdx.x * 256 + threadIdx.x;   // over NALL
    if (idx < G6) g_biaslr[idx] = bl[idx] + br[idx];
    if (idx < NALL) g_biasA[idx] = (idx < G6) ? bx[idx] : bp[idx - G6];
    if (idx < HDIM) {
        size_t s = (size_t)N_OBJ * HDIM + idx;
        g_C[s] = 0.f; g_H[s] = 0.f;
        g_He[s] = __float2half_rn(0.f);
    }
}

// ---------------- fp16 mma GEMM: C = A @ B^T (+bias) -------------------------
// A, B: single fp16 planes, row stride 2048.
// Stage = BK64 = two 32-wide sub-tiles, 3 stages; BN=128, BM in {128, 64}.
// Split-K: blockIdx.z = part p handles pairs [p*ppp, (p+1)*ppp), writes slab
// C + p*M*N. Deterministic.
template <int BM>
__global__ __launch_bounds__(256, 2) void gemm_hf(
    const __half* __restrict__ A, const __half* __restrict__ B,
    const float* __restrict__ bias, float* __restrict__ C, int M, int N, int ppp)
{
    constexpr int WCOLS = (BM == 128) ? 4 : 8;
    constexpr int WN = 128 / WCOLS;           // 32 / 16
    constexpr int NF = WN / 8;                // 4 / 2
    constexpr int ATB = BM * 64;              // A sub-tile bytes
    constexpr int SUB = ATB + 8192;           // A+B sub-tile
    constexpr int STAGE = 2 * SUB;            // BK64 stage bytes

    extern __shared__ char smem[];
    const uint32_t sb = smem_to_u32(smem);
    const int tid = threadIdx.x, lane = tid & 31, warp = tid >> 5;
    const int wr_ = warp / WCOLS, wc_ = warp % WCOLS;

    const int part = blockIdx.z;
    C += (size_t)part * M * N;
    const int p0 = part * ppp;

    // ---- L2-aware tile swizzle (within a part) ----
    const int tiles_n = gridDim.x, tiles_m = gridDim.y;
    int lid = blockIdx.y * tiles_n + blockIdx.x;
    const int GRP = 8;
    int per_group = GRP * tiles_m;
    int grp = lid / per_group, rem = lid - grp * per_group;
    int nt0 = grp * GRP;
    int gn = tiles_n - nt0; if (gn > GRP) gn = GRP;
    int nt = nt0 + rem % gn;
    int mt = rem / gn;
    const int row0 = mt * BM, col0 = nt * 128;

    // ldmatrix lane geometry
    const int lrow = ((lane >> 3) & 1) * 8 + (lane & 7);
    const int lcol = lane >> 4;

    // cp.async op coords
    const int r_op0 = tid >> 2,         ch0 = tid & 3;
    const int r_op1 = (tid + 256) >> 2, ch1 = tid & 3;

    float acc[4][NF][4];
#pragma unroll
    for (int a = 0; a < 4; a++)
#pragma unroll
        for (int b = 0; b < NF; b++)
#pragma unroll
            for (int t = 0; t < 4; t++) acc[a][b][t] = 0.f;

    // load one 32-wide k-chunk c into sub-slot (A @ off, B @ off+ATB)
    auto load_sub = [&](int c, uint32_t off) {
        const __half* Ab = A + (size_t)c * 32;
        const __half* Bb = B + (size_t)c * 32;
        uint32_t sA = sb + off, sBm = sA + ATB;
        cpasync16(sA + swz(r_op0, ch0), Ab + (size_t)(row0 + r_op0) * 2048 + ch0 * 8);
        if (BM == 128)
            cpasync16(sA + swz(r_op1, ch1), Ab + (size_t)(row0 + r_op1) * 2048 + ch1 * 8);
        cpasync16(sBm + swz(r_op0, ch0), Bb + (size_t)(col0 + r_op0) * 2048 + ch0 * 8);
        cpasync16(sBm + swz(r_op1, ch1), Bb + (size_t)(col0 + r_op1) * 2048 + ch1 * 8);
    };
    auto load_pair = [&](int p, int st) {
        load_sub(2 * p,     (uint32_t)(st * STAGE));
        load_sub(2 * p + 1, (uint32_t)(st * STAGE + SUB));
        asm volatile("cp.async.commit_group;" ::: "memory");
    };
    // fragment load for k16 step kk (0..3) of stage st
    auto ldfrag = [&](int st, int kk, uint32_t af[4][4], uint32_t bq[2][4]) {
        uint32_t sA = sb + st * STAGE + (kk >> 1) * SUB;
        uint32_t sBm = sA + ATB;
        int kl = (kk & 1) * 2 + lcol;
#pragma unroll
        for (int mf = 0; mf < 4; mf++) {
            int r = wr_ * 64 + mf * 16 + lrow;
            ldmx4(af[mf], sA + swz(r, kl));
        }
#pragma unroll
        for (int bh = 0; bh < WN / 16; bh++) {
            int r = wc_ * WN + bh * 16 + lrow;
            ldmx4(bq[bh], sBm + swz(r, kl));
        }
    };

    load_pair(p0, 0); load_pair(p0 + 1, 1);

    uint32_t fA[2][4][4], fB[2][2][4];

    for (int i = 0; i < ppp; i++) {
        int st = i % 3;
        if (i + 2 < ppp) {
            asm volatile("cp.async.wait_group 1;" ::: "memory");
        } else {
            asm volatile("cp.async.wait_group 0;" ::: "memory");   // tail drain
        }
        __syncthreads();
        if (i + 2 < ppp) load_pair(p0 + i + 2, (i + 2) % 3);

        ldfrag(st, 0, fA[0], fB[0]);
#pragma unroll
        for (int kk = 0; kk < 4; kk++) {
            if (kk < 3) ldfrag(st, kk + 1, fA[(kk + 1) & 1], fB[(kk + 1) & 1]);
            uint32_t (*af)[4] = fA[kk & 1];
            uint32_t (*bq)[4] = fB[kk & 1];
#pragma unroll
            for (int mf = 0; mf < 4; mf++)
#pragma unroll
                for (int nf = 0; nf < NF; nf++) {
                    uint32_t b2[2] = { bq[nf >> 1][nf & 1], bq[nf >> 1][2 + (nf & 1)] };
                    mma_f16(acc[mf][nf], af[mf], b2);
                }
        }
    }

    // ---- epilogue ----
#pragma unroll
    for (int mf = 0; mf < 4; mf++) {
#pragma unroll
        for (int nf = 0; nf < NF; nf++) {
            int r  = row0 + wr_ * 64 + mf * 16 + (lane >> 2);
            int cb = col0 + wc_ * WN + nf * 8 + (lane & 3) * 2;
            float b0 = bias ? bias[cb] : 0.f;
            float b1 = bias ? bias[cb + 1] : 0.f;
            if (r < M) {
                C[(size_t)r * N + cb]     = acc[mf][nf][0] + b0;
                C[(size_t)r * N + cb + 1] = acc[mf][nf][1] + b1;
            }
            if (r + 8 < M) {
                C[(size_t)(r + 8) * N + cb]     = acc[mf][nf][2] + b0;
                C[(size_t)(r + 8) * N + cb + 1] = acc[mf][nf][3] + b1;
            }
        }
    }
}

// ---------------- tiny-M GEMM (M<=16): A fp32, B fp16; warp per column -------
__global__ void gemm_small_h(const float* __restrict__ A, const __half* __restrict__ B,
                             float* __restrict__ C, int M, int N, int K)
{
    int warp = threadIdx.x >> 5, lane = threadIdx.x & 31;
    int n = blockIdx.x * 8 + warp;
    if (n >= N) return;
    float acc[16];
#pragma unroll
    for (int m = 0; m < 16; m++) acc[m] = 0.f;
    const __half* Brow = B + (size_t)n * K;
    for (int k = lane * 8; k < K; k += 256) {
        // 8 halfs = 16B
        uint4 braw = *(const uint4*)(Brow + k);
        float2 b01 = __half22float2(*(__half2*)&braw.x);
        float2 b23 = __half22float2(*(__half2*)&braw.y);
        float2 b45 = __half22float2(*(__half2*)&braw.z);
        float2 b67 = __half22float2(*(__half2*)&braw.w);
#pragma unroll
        for (int m = 0; m < 16; m++) {
            if (m < M) {
                float4 a0 = *(const float4*)(A + (size_t)m * K + k);
                float4 a1 = *(const float4*)(A + (size_t)m * K + k + 4);
                acc[m] += a0.x * b01.x + a0.y * b01.y + a0.z * b23.x + a0.w * b23.y
                        + a1.x * b45.x + a1.y * b45.y + a1.z * b67.x + a1.w * b67.y;
            }
        }
    }
#pragma unroll
    for (int m = 0; m < 16; m++) {
        if (m < M) {
            float v = acc[m];
#pragma unroll
            for (int off = 16; off; off >>= 1) v += __shfl_xor_sync(~0u, v, off);
            if (lane == 0) C[(size_t)m * N + n] = v;
        }
    }
}

// ---------------- pointwise LSTM cell for one wavefront ----------------------
__device__ __forceinline__ float sigm(float x) { return 1.f / (1.f + expf(-x)); }

__global__ void pointwise(int s, int M, const float* __restrict__ Gh,
                          int nparts, int pstride, float* __restrict__ out)
{
    int idx = blockIdx.x * blockDim.x + threadIdx.x;
    if (idx >= M * HDIM) return;
    int m = idx >> 10;
    int j = idx & (HDIM - 1);
    int n = s + m;

    const float* xg = g_XGP + (size_t)n * NALL;
    float g[6];
#pragma unroll
    for (int t = 0; t < 6; t++) {
        int o = t * HDIM + j;
        float v = xg[o] + g_biaslr[o];
        for (int p = 0; p < nparts; p++)
            v += Gh[(size_t)p * pstride + (size_t)m * G6 + o];
        g[t] = v;
    }
    float ig = sigm(g[0]), og = sigm(g[1]);
    float fl = sigm(g[2]), fr = sigm(g[3]);
    float u  = tanhf(g[4]), rr = sigm(g[5]);

    int l = 2 * n + 1; if (l > N_OBJ) l = N_OBJ;
    int r = 2 * n + 2; if (r > N_OBJ) r = N_OBJ;

    float c = ig * u + fl * g_C[(size_t)l * HDIM + j] + fr * g_C[(size_t)r * HDIM + j];
    float h = og * tanhf(c);
    float hf = rr * h + (1.f - rr) * xg[G6 + j];     // px fused at cols [6144,7168)

    size_t o = (size_t)n * HDIM + j;
    g_C[o] = c;
    g_H[o] = hf;
    out[o] = hf;
    g_He[o] = __float2half_rn(hf);
}

// ---------------- launcher ---------------------------------------------------
extern "C" void kernel_launch(void* const* d_in, const int* in_sizes, int n_in,
                              void* d_out, int out_size)
{
    const float* features = (const float*)d_in[0];
    const float* w_iox    = (const float*)d_in[1];
    const float* b_iox    = (const float*)d_in[2];
    const float* w_l      = (const float*)d_in[3];
    const float* b_l      = (const float*)d_in[4];
    const float* w_r      = (const float*)d_in[5];
    const float* b_r      = (const float*)d_in[6];
    const float* w_px     = (const float*)d_in[7];
    const float* b_px     = (const float*)d_in[8];
    float* out = (float*)d_out;

    float *XGP, *Gh, *Htab, *biasA;
    __half *Fe, *WAe, *Wce, *He;
    cudaGetSymbolAddress((void**)&XGP,   g_XGP);
    cudaGetSymbolAddress((void**)&Gh,    g_Gh);
    cudaGetSymbolAddress((void**)&Htab,  g_H);
    cudaGetSymbolAddress((void**)&biasA, g_biasA);
    cudaGetSymbolAddress((void**)&Fe,    g_Fe);
    cudaGetSymbolAddress((void**)&WAe,   g_WAe);
    cudaGetSymbolAddress((void**)&Wce,   g_Wce);
    cudaGetSymbolAddress((void**)&He,    g_He);

    const int SMEM_128 = 3 * 32768;
    const int SMEM_64  = 3 * 24576;
    cudaFuncSetAttribute(gemm_hf<128>, cudaFuncAttributeMaxDynamicSharedMemorySize, SMEM_128);
    cudaFuncSetAttribute(gemm_hf<64>,  cudaFuncAttributeMaxDynamicSharedMemorySize, SMEM_64);

    // prep + single-plane fp16 expansion
    prep_kernel<<<(NALL + 255) / 256, 256>>>(b_l, b_r, b_iox, b_px);
    expand1_kernel<<<(int)((PS_F + 255) / 256), 256>>>(features, Fe, (int)PS_F);
    expand1_kernel<<<(int)(((size_t)G6 * FDIM + 255) / 256), 256>>>(
        w_iox, WAe, (int)((size_t)G6 * FDIM));
    expand1_kernel<<<(int)(((size_t)HDIM * FDIM + 255) / 256), 256>>>(
        w_px, WAe + (size_t)G6 * FDIM, (int)((size_t)HDIM * FDIM));
    expand_wc_kernel<<<(int)((PS_WC + 255) / 256), 256>>>(w_l, w_r);

    // phase A: fused [XG | PX] GEMM, N = 7168
    gemm_hf<128><<<dim3(NALL / 128, N_OBJ / 128, 1), 256, SMEM_128>>>(
        Fe, WAe, biasA, XGP, N_OBJ, NALL, NPAIR);

    // leaves
    pointwise<<<(1024 * HDIM + 255) / 256, 256>>>(1024, 1024, nullptr, 0, 0, out);

    // node 1023 (single; A fp32 rows 2047 + sentinel 2048, B fp16)
    gemm_small_h<<<G6 / 8, 256>>>(Htab + (size_t)2047 * HDIM, Wce, Gh, 1, G6, KCAT);
    pointwise<<<(1 * HDIM + 255) / 256, 256>>>(1023, 1, Gh, 1, 0, out);

    // big internal wavefronts with deterministic split-K (wave-packed KS)
    struct Lv { int s, M, KS, BM; };
    const Lv big[5] = { {511, 512, 2, 128}, {255, 256, 4, 128}, {127, 128, 4, 128},
                        {63, 64, 4, 64}, {31, 32, 4, 64} };
    for (int li = 0; li < 5; li++) {
        int s = big[li].s, M = big[li].M, KS = big[li].KS;
        const __half* Ab = He + (size_t)(2 * s + 1) * HDIM;
        if (big[li].BM == 128) {
            int Mtiles = (M + 127) / 128;
            gemm_hf<128><<<dim3(G6 / 128, Mtiles, KS), 256, SMEM_128>>>(
                Ab, Wce, nullptr, Gh, M, G6, NPAIR / KS);
        } else {
            gemm_hf<64><<<dim3(G6 / 128, 1, KS), 256, SMEM_64>>>(
                Ab, Wce, nullptr, Gh, M, G6, NPAIR / KS);
        }
        pointwise<<<(M * HDIM + 255) / 256, 256>>>(s, M, Gh, KS, M * G6, out);
    }

    // tiny wavefronts (fp32 A x fp16 B warp-dot)
    const Lv small_[5] = { {15, 16, 0, 0}, {7, 8, 0, 0}, {3, 4, 0, 0},
                           {1, 2, 0, 0}, {0, 1, 0, 0} };
    for (int li = 0; li < 5; li++) {
        int s = small_[li].s, M = small_[li].M;
        gemm_small_h<<<G6 / 8, 256>>>(Htab + (size_t)(2 * s + 1) * HDIM, Wce, Gh, M, G6, KCAT);
        pointwise<<<(M * HDIM + 255) / 256, 256>>>(s, M, Gh, 1, 0, out);
    }
}

// round 15
// speedup vs baseline: 2.0579x; 1.0222x over previous
#include <cuda_runtime.h>
#include <cuda_fp16.h>
#include <math.h>
#include <stdint.h>

#define N_OBJ 2048
#define FDIM  2048
#define HDIM  1024
#define G6    6144          // 6*HDIM
#define NALL  7168          // 6*HDIM + HDIM (fused XG|PX width)
#define KCAT  2048          // 2*HDIM
#define NPAIR 32            // (2048/64) BK64 pairs total

// plane strides (elements)
#define PS_F  ((size_t)N_OBJ * FDIM)
#define PS_WA ((size_t)NALL * FDIM)
#define PS_WC ((size_t)G6 * KCAT)
#define PS_H  ((size_t)(N_OBJ + 1) * HDIM)

// ---------------- scratch (static device globals; no allocation) -------------
__device__ float g_XGP[(size_t)N_OBJ * NALL];        // [XG | PX] fused
__device__ float g_biaslr[G6];
__device__ float g_biasA[NALL];                      // b_iox | b_px
__device__ float g_C[(size_t)(N_OBJ + 1) * HDIM];
__device__ float g_H[(size_t)(N_OBJ + 1) * HDIM];
__device__ float g_Gh[(size_t)2048 * G6];            // split-K partial slabs

// fp16 operand planes (single plane each side)
__device__ __half g_Fe [PS_F];                       // features
__device__ __half g_WAe[PS_WA];                      // [w_iox; w_px]
__device__ __half g_Wce[PS_WC];                      // [Wl | Wr]
__device__ __half g_He [PS_H];                       // hidden

// grid-barrier state for the persistent tail kernel
__device__ unsigned g_bar_count = 0;
__device__ unsigned g_bar_gen = 0;

// ---------------- helpers ----------------------------------------------------
__device__ __forceinline__ uint32_t smem_to_u32(const void* p) {
    uint32_t a;
    asm("{ .reg .u64 t; cvta.to.shared.u64 t, %1; cvt.u32.u64 %0, t; }" : "=r"(a) : "l"(p));
    return a;
}
__device__ __forceinline__ void ldmx4(uint32_t* d, uint32_t addr) {
    asm volatile("ldmatrix.sync.aligned.m8n8.x4.shared.b16 {%0,%1,%2,%3}, [%4];"
                 : "=r"(d[0]), "=r"(d[1]), "=r"(d[2]), "=r"(d[3]) : "r"(addr));
}
__device__ __forceinline__ void mma_f16(float* c, const uint32_t* a, const uint32_t* b) {
    asm volatile("mma.sync.aligned.m16n8k16.row.col.f32.f16.f16.f32 "
                 "{%0,%1,%2,%3}, {%4,%5,%6,%7}, {%8,%9}, {%0,%1,%2,%3};"
                 : "+f"(c[0]), "+f"(c[1]), "+f"(c[2]), "+f"(c[3])
                 : "r"(a[0]), "r"(a[1]), "r"(a[2]), "r"(a[3]), "r"(b[0]), "r"(b[1]));
}
__device__ __forceinline__ void cpasync16(uint32_t dst, const void* src) {
    asm volatile("cp.async.cg.shared.global [%0], [%1], 16;" :: "r"(dst), "l"(src));
}

// swizzle: 16B chunk x (0..3) within a 64B row r -> conflict-free for both
// cp.async stores and ldmatrix reads.
__device__ __forceinline__ uint32_t swz(int r, int x) {
    return (uint32_t)(r * 64 + ((x ^ ((r >> 1) & 3)) << 4));
}

__device__ __forceinline__ float sigm(float x) { return 1.f / (1.f + expf(-x)); }

// ---------------- expansion kernels ------------------------------------------
__global__ void expand1_kernel(const float* __restrict__ src, __half* __restrict__ dst,
                               int total)
{
    int i = blockIdx.x * 256 + threadIdx.x;
    if (i < total) dst[i] = __float2half_rn(src[i]);
}

// build fp16 [Wl | Wr] concat directly from inputs
__global__ void expand_wc_kernel(const float* __restrict__ wl, const float* __restrict__ wr)
{
    int idx = blockIdx.x * 256 + threadIdx.x;   // over G6*KCAT
    int j = idx >> 11;
    int k = idx & (KCAT - 1);
    float w = (k < HDIM) ? wl[(size_t)j * HDIM + k] : wr[(size_t)j * HDIM + (k - HDIM)];
    g_Wce[idx] = __float2half_rn(w);
}

// ---------------- prep: biases + sentinel rows -------------------------------
__global__ void prep_kernel(const float* __restrict__ bl, const float* __restrict__ br,
                            const float* __restrict__ bx, const float* __restrict__ bp)
{
    int idx = blockIdx.x * 256 + threadIdx.x;   // over NALL
    if (idx < G6) g_biaslr[idx] = bl[idx] + br[idx];
    if (idx < NALL) g_biasA[idx] = (idx < G6) ? bx[idx] : bp[idx - G6];
    if (idx < HDIM) {
        size_t s = (size_t)N_OBJ * HDIM + idx;
        g_C[s] = 0.f; g_H[s] = 0.f;
        g_He[s] = __float2half_rn(0.f);
    }
}

// ---------------- fp16 mma GEMM: C = A @ B^T (+bias) -------------------------
// A, B: single fp16 planes, row stride 2048.
// Stage = BK64 = two 32-wide sub-tiles, 3 stages; BN=128, BM in {128, 64}.
// Split-K (non-uniform): part p handles pairs [p*ppp, min((p+1)*ppp, NPAIR)),
// writes slab C + p*M*N. Deterministic.
template <int BM>
__global__ __launch_bounds__(256, 2) void gemm_hf(
    const __half* __restrict__ A, const __half* __restrict__ B,
    const float* __restrict__ bias, float* __restrict__ C, int M, int N, int ppp)
{
    constexpr int WCOLS = (BM == 128) ? 4 : 8;
    constexpr int WN = 128 / WCOLS;           // 32 / 16
    constexpr int NF = WN / 8;                // 4 / 2
    constexpr int ATB = BM * 64;              // A sub-tile bytes
    constexpr int SUB = ATB + 8192;           // A+B sub-tile
    constexpr int STAGE = 2 * SUB;            // BK64 stage bytes

    extern __shared__ char smem[];
    const uint32_t sb = smem_to_u32(smem);
    const int tid = threadIdx.x, lane = tid & 31, warp = tid >> 5;
    const int wr_ = warp / WCOLS, wc_ = warp % WCOLS;

    const int part = blockIdx.z;
    C += (size_t)part * M * N;
    const int p0 = part * ppp;
    int cnt = NPAIR - p0; if (cnt > ppp) cnt = ppp;   // non-uniform tail part

    // ---- L2-aware tile swizzle (within a part) ----
    const int tiles_n = gridDim.x, tiles_m = gridDim.y;
    int lid = blockIdx.y * tiles_n + blockIdx.x;
    const int GRP = 8;
    int per_group = GRP * tiles_m;
    int grp = lid / per_group, rem = lid - grp * per_group;
    int nt0 = grp * GRP;
    int gn = tiles_n - nt0; if (gn > GRP) gn = GRP;
    int nt = nt0 + rem % gn;
    int mt = rem / gn;
    const int row0 = mt * BM, col0 = nt * 128;

    // ldmatrix lane geometry
    const int lrow = ((lane >> 3) & 1) * 8 + (lane & 7);
    const int lcol = lane >> 4;

    // cp.async op coords
    const int r_op0 = tid >> 2,         ch0 = tid & 3;
    const int r_op1 = (tid + 256) >> 2, ch1 = tid & 3;

    float acc[4][NF][4];
#pragma unroll
    for (int a = 0; a < 4; a++)
#pragma unroll
        for (int b = 0; b < NF; b++)
#pragma unroll
            for (int t = 0; t < 4; t++) acc[a][b][t] = 0.f;

    // load one 32-wide k-chunk c into sub-slot (A @ off, B @ off+ATB)
    auto load_sub = [&](int c, uint32_t off) {
        const __half* Ab = A + (size_t)c * 32;
        const __half* Bb = B + (size_t)c * 32;
        uint32_t sA = sb + off, sBm = sA + ATB;
        cpasync16(sA + swz(r_op0, ch0), Ab + (size_t)(row0 + r_op0) * 2048 + ch0 * 8);
        if (BM == 128)
            cpasync16(sA + swz(r_op1, ch1), Ab + (size_t)(row0 + r_op1) * 2048 + ch1 * 8);
        cpasync16(sBm + swz(r_op0, ch0), Bb + (size_t)(col0 + r_op0) * 2048 + ch0 * 8);
        cpasync16(sBm + swz(r_op1, ch1), Bb + (size_t)(col0 + r_op1) * 2048 + ch1 * 8);
    };
    auto load_pair = [&](int p, int st) {
        load_sub(2 * p,     (uint32_t)(st * STAGE));
        load_sub(2 * p + 1, (uint32_t)(st * STAGE + SUB));
        asm volatile("cp.async.commit_group;" ::: "memory");
    };
    // fragment load for k16 step kk (0..3) of stage st
    auto ldfrag = [&](int st, int kk, uint32_t af[4][4], uint32_t bq[2][4]) {
        uint32_t sA = sb + st * STAGE + (kk >> 1) * SUB;
        uint32_t sBm = sA + ATB;
        int kl = (kk & 1) * 2 + lcol;
#pragma unroll
        for (int mf = 0; mf < 4; mf++) {
            int r = wr_ * 64 + mf * 16 + lrow;
            ldmx4(af[mf], sA + swz(r, kl));
        }
#pragma unroll
        for (int bh = 0; bh < WN / 16; bh++) {
            int r = wc_ * WN + bh * 16 + lrow;
            ldmx4(bq[bh], sBm + swz(r, kl));
        }
    };

    load_pair(p0, 0);
    if (cnt > 1) load_pair(p0 + 1, 1);

    uint32_t fA[2][4][4], fB[2][2][4];

    for (int i = 0; i < cnt; i++) {
        int st = i % 3;
        if (i + 2 < cnt) {
            asm volatile("cp.async.wait_group 1;" ::: "memory");
        } else {
            asm volatile("cp.async.wait_group 0;" ::: "memory");   // tail drain
        }
        __syncthreads();
        if (i + 2 < cnt) load_pair(p0 + i + 2, (i + 2) % 3);

        ldfrag(st, 0, fA[0], fB[0]);
#pragma unroll
        for (int kk = 0; kk < 4; kk++) {
            if (kk < 3) ldfrag(st, kk + 1, fA[(kk + 1) & 1], fB[(kk + 1) & 1]);
            uint32_t (*af)[4] = fA[kk & 1];
            uint32_t (*bq)[4] = fB[kk & 1];
#pragma unroll
            for (int mf = 0; mf < 4; mf++)
#pragma unroll
                for (int nf = 0; nf < NF; nf++) {
                    uint32_t b2[2] = { bq[nf >> 1][nf & 1], bq[nf >> 1][2 + (nf & 1)] };
                    mma_f16(acc[mf][nf], af[mf], b2);
                }
        }
    }

    // ---- epilogue ----
#pragma unroll
    for (int mf = 0; mf < 4; mf++) {
#pragma unroll
        for (int nf = 0; nf < NF; nf++) {
            int r  = row0 + wr_ * 64 + mf * 16 + (lane >> 2);
            int cb = col0 + wc_ * WN + nf * 8 + (lane & 3) * 2;
            float b0 = bias ? bias[cb] : 0.f;
            float b1 = bias ? bias[cb + 1] : 0.f;
            if (r < M) {
                C[(size_t)r * N + cb]     = acc[mf][nf][0] + b0;
                C[(size_t)r * N + cb + 1] = acc[mf][nf][1] + b1;
            }
            if (r + 8 < M) {
                C[(size_t)(r + 8) * N + cb]     = acc[mf][nf][2] + b0;
                C[(size_t)(r + 8) * N + cb + 1] = acc[mf][nf][3] + b1;
            }
        }
    }
}

// ---------------- tiny-M GEMM (M<=16): A fp32, B fp16; warp per column -------
__global__ void gemm_small_h(const float* __restrict__ A, const __half* __restrict__ B,
                             float* __restrict__ C, int M, int N, int K)
{
    int warp = threadIdx.x >> 5, lane = threadIdx.x & 31;
    int n = blockIdx.x * 8 + warp;
    if (n >= N) return;
    float acc[16];
#pragma unroll
    for (int m = 0; m < 16; m++) acc[m] = 0.f;
    const __half* Brow = B + (size_t)n * K;
    for (int k = lane * 8; k < K; k += 256) {
        uint4 braw = *(const uint4*)(Brow + k);
        float2 b01 = __half22float2(*(__half2*)&braw.x);
        float2 b23 = __half22float2(*(__half2*)&braw.y);
        float2 b45 = __half22float2(*(__half2*)&braw.z);
        float2 b67 = __half22float2(*(__half2*)&braw.w);
#pragma unroll
        for (int m = 0; m < 16; m++) {
            if (m < M) {
                float4 a0 = *(const float4*)(A + (size_t)m * K + k);
                float4 a1 = *(const float4*)(A + (size_t)m * K + k + 4);
                acc[m] += a0.x * b01.x + a0.y * b01.y + a0.z * b23.x + a0.w * b23.y
                        + a1.x * b45.x + a1.y * b45.y + a1.z * b67.x + a1.w * b67.y;
            }
        }
    }
#pragma unroll
    for (int m = 0; m < 16; m++) {
        if (m < M) {
            float v = acc[m];
#pragma unroll
            for (int off = 16; off; off >>= 1) v += __shfl_xor_sync(~0u, v, off);
            if (lane == 0) C[(size_t)m * N + n] = v;
        }
    }
}

// ---------------- pointwise LSTM cell for one wavefront ----------------------
__global__ void pointwise(int s, int M, const float* __restrict__ Gh,
                          int nparts, int pstride, float* __restrict__ out)
{
    int idx = blockIdx.x * blockDim.x + threadIdx.x;
    if (idx >= M * HDIM) return;
    int m = idx >> 10;
    int j = idx & (HDIM - 1);
    int n = s + m;

    const float* xg = g_XGP + (size_t)n * NALL;
    float g[6];
#pragma unroll
    for (int t = 0; t < 6; t++) {
        int o = t * HDIM + j;
        float v = xg[o] + g_biaslr[o];
        for (int p = 0; p < nparts; p++)
            v += Gh[(size_t)p * pstride + (size_t)m * G6 + o];
        g[t] = v;
    }
    float ig = sigm(g[0]), og = sigm(g[1]);
    float fl = sigm(g[2]), fr = sigm(g[3]);
    float u  = tanhf(g[4]), rr = sigm(g[5]);

    int l = 2 * n + 1; if (l > N_OBJ) l = N_OBJ;
    int r = 2 * n + 2; if (r > N_OBJ) r = N_OBJ;

    float c = ig * u + fl * g_C[(size_t)l * HDIM + j] + fr * g_C[(size_t)r * HDIM + j];
    float h = og * tanhf(c);
    float hf = rr * h + (1.f - rr) * xg[G6 + j];     // px fused at cols [6144,7168)

    size_t o = (size_t)n * HDIM + j;
    g_C[o] = c;
    g_H[o] = hf;
    out[o] = hf;
    g_He[o] = __float2half_rn(hf);
}

// ---------------- persistent fused tail: levels M=16..1 ----------------------
// 296 CTAs (2/SM, co-residency guaranteed: 0 smem, <=128 regs via launch
// bounds). Generation-counter grid barrier; deterministic output.
__device__ __forceinline__ void grid_barrier()
{
    __syncthreads();
    if (threadIdx.x == 0) {
        __threadfence();
        unsigned gen = *((volatile unsigned*)&g_bar_gen);
        unsigned ticket = atomicAdd(&g_bar_count, 1);
        if (ticket == gridDim.x - 1) {
            g_bar_count = 0;
            __threadfence();
            atomicAdd(&g_bar_gen, 1);
        } else {
            while (*((volatile unsigned*)&g_bar_gen) == gen) __nanosleep(64);
        }
        __threadfence();
    }
    __syncthreads();
}

__global__ __launch_bounds__(256, 2) void tail_kernel(float* __restrict__ out)
{
    const int tid = threadIdx.x;
    const int warp = tid >> 5, lane = tid & 31;
    const int sv[5] = {15, 7, 3, 1, 0};
    const int Mv[5] = {16, 8, 4, 2, 1};

    for (int li = 0; li < 5; li++) {
        const int s = sv[li], M = Mv[li];
        const float* A = g_H + (size_t)(2 * s + 1) * HDIM;   // [M rows x 2048]

        // ---- GEMM: g_Gh[m][n] = sum_k A[m][k] * Wce[n][k] ----
        for (int n = blockIdx.x * 8 + warp; n < G6; n += gridDim.x * 8) {
            float acc[16];
#pragma unroll
            for (int m = 0; m < 16; m++) acc[m] = 0.f;
            const __half* Brow = g_Wce + (size_t)n * KCAT;
            for (int k = lane * 8; k < KCAT; k += 256) {
                uint4 braw = *(const uint4*)(Brow + k);
                float2 b01 = __half22float2(*(__half2*)&braw.x);
                float2 b23 = __half22float2(*(__half2*)&braw.y);
                float2 b45 = __half22float2(*(__half2*)&braw.z);
                float2 b67 = __half22float2(*(__half2*)&braw.w);
#pragma unroll
                for (int m = 0; m < 16; m++) {
                    if (m < M) {
                        float4 a0 = *(const float4*)(A + (size_t)m * KCAT + k);
                        float4 a1 = *(const float4*)(A + (size_t)m * KCAT + k + 4);
                        acc[m] += a0.x * b01.x + a0.y * b01.y + a0.z * b23.x + a0.w * b23.y
                                + a1.x * b45.x + a1.y * b45.y + a1.z * b67.x + a1.w * b67.y;
                    }
                }
            }
#pragma unroll
            for (int m = 0; m < 16; m++) {
                if (m < M) {
                    float v = acc[m];
#pragma unroll
                    for (int off = 16; off; off >>= 1) v += __shfl_xor_sync(~0u, v, off);
                    if (lane == 0) g_Gh[(size_t)m * G6 + n] = v;
                }
            }
        }
        grid_barrier();

        // ---- pointwise ----
        for (int idx = blockIdx.x * 256 + tid; idx < M * HDIM; idx += gridDim.x * 256) {
            int m = idx >> 10;
            int j = idx & (HDIM - 1);
            int n = s + m;
            const float* xg = g_XGP + (size_t)n * NALL;
            float g[6];
#pragma unroll
            for (int t = 0; t < 6; t++) {
                int o = t * HDIM + j;
                g[t] = xg[o] + g_biaslr[o] + g_Gh[(size_t)m * G6 + o];
            }
            float ig = sigm(g[0]), og = sigm(g[1]);
            float fl = sigm(g[2]), fr = sigm(g[3]);
            float u  = tanhf(g[4]), rr = sigm(g[5]);
            int l = 2 * n + 1, r = 2 * n + 2;        // always <= 2046 here
            float c = ig * u + fl * g_C[(size_t)l * HDIM + j]
                             + fr * g_C[(size_t)r * HDIM + j];
            float h = og * tanhf(c);
            float hf = rr * h + (1.f - rr) * xg[G6 + j];
            size_t o = (size_t)n * HDIM + j;
            g_C[o] = c;
            g_H[o] = hf;
            out[o] = hf;
        }
        grid_barrier();
    }
}

// ---------------- launcher ---------------------------------------------------
extern "C" void kernel_launch(void* const* d_in, const int* in_sizes, int n_in,
                              void* d_out, int out_size)
{
    const float* features = (const float*)d_in[0];
    const float* w_iox    = (const float*)d_in[1];
    const float* b_iox    = (const float*)d_in[2];
    const float* w_l      = (const float*)d_in[3];
    const float* b_l      = (const float*)d_in[4];
    const float* w_r      = (const float*)d_in[5];
    const float* b_r      = (const float*)d_in[6];
    const float* w_px     = (const float*)d_in[7];
    const float* b_px     = (const float*)d_in[8];
    float* out = (float*)d_out;

    float *XGP, *Gh, *Htab, *biasA;
    __half *Fe, *WAe, *Wce, *He;
    cudaGetSymbolAddress((void**)&XGP,   g_XGP);
    cudaGetSymbolAddress((void**)&Gh,    g_Gh);
    cudaGetSymbolAddress((void**)&Htab,  g_H);
    cudaGetSymbolAddress((void**)&biasA, g_biasA);
    cudaGetSymbolAddress((void**)&Fe,    g_Fe);
    cudaGetSymbolAddress((void**)&WAe,   g_WAe);
    cudaGetSymbolAddress((void**)&Wce,   g_Wce);
    cudaGetSymbolAddress((void**)&He,    g_He);

    const int SMEM_128 = 3 * 32768;
    const int SMEM_64  = 3 * 24576;
    cudaFuncSetAttribute(gemm_hf<128>, cudaFuncAttributeMaxDynamicSharedMemorySize, SMEM_128);
    cudaFuncSetAttribute(gemm_hf<64>,  cudaFuncAttributeMaxDynamicSharedMemorySize, SMEM_64);

    // prep + single-plane fp16 expansion
    prep_kernel<<<(NALL + 255) / 256, 256>>>(b_l, b_r, b_iox, b_px);
    expand1_kernel<<<(int)((PS_F + 255) / 256), 256>>>(features, Fe, (int)PS_F);
    expand1_kernel<<<(int)(((size_t)G6 * FDIM + 255) / 256), 256>>>(
        w_iox, WAe, (int)((size_t)G6 * FDIM));
    expand1_kernel<<<(int)(((size_t)HDIM * FDIM + 255) / 256), 256>>>(
        w_px, WAe + (size_t)G6 * FDIM, (int)((size_t)HDIM * FDIM));
    expand_wc_kernel<<<(int)((PS_WC + 255) / 256), 256>>>(w_l, w_r);

    // phase A: fused [XG | PX] GEMM, N = 7168
    gemm_hf<128><<<dim3(NALL / 128, N_OBJ / 128, 1), 256, SMEM_128>>>(
        Fe, WAe, biasA, XGP, N_OBJ, NALL, NPAIR);

    // leaves
    pointwise<<<(1024 * HDIM + 255) / 256, 256>>>(1024, 1024, nullptr, 0, 0, out);

    // node 1023 (single; A fp32 rows 2047 + sentinel 2048, B fp16)
    gemm_small_h<<<G6 / 8, 256>>>(Htab + (size_t)2047 * HDIM, Wce, Gh, 1, G6, KCAT);
    pointwise<<<(1 * HDIM + 255) / 256, 256>>>(1023, 1, Gh, 1, 0, out);

    // big internal wavefronts, deterministic non-uniform split-K (wave-packed)
    struct Lv { int s, M, KS, BM; };
    const Lv big[5] = { {511, 512, 3, 128}, {255, 256, 3, 128}, {127, 128, 6, 128},
                        {63, 64, 6, 64}, {31, 32, 6, 64} };
    for (int li = 0; li < 5; li++) {
        int s = big[li].s, M = big[li].M, KS = big[li].KS;
        int ppp = (NPAIR + KS - 1) / KS;
        const __half* Ab = He + (size_t)(2 * s + 1) * HDIM;
        if (big[li].BM == 128) {
            int Mtiles = (M + 127) / 128;
            gemm_hf<128><<<dim3(G6 / 128, Mtiles, KS), 256, SMEM_128>>>(
                Ab, Wce, nullptr, Gh, M, G6, ppp);
        } else {
            gemm_hf<64><<<dim3(G6 / 128, 1, KS), 256, SMEM_64>>>(
                Ab, Wce, nullptr, Gh, M, G6, ppp);
        }
        pointwise<<<(M * HDIM + 255) / 256, 256>>>(s, M, Gh, KS, M * G6, out);
    }

    // fused persistent tail: levels M=16,8,4,2,1 (10 launches -> 1)
    tail_kernel<<<296, 256>>>(out);
}

// round 16
// speedup vs baseline: 2.0580x; 1.0000x over previous
#include <cuda_runtime.h>
#include <cuda_fp16.h>
#include <math.h>
#include <stdint.h>

#define N_OBJ 2048
#define FDIM  2048
#define HDIM  1024
#define G6    6144          // 6*HDIM
#define NALL  7168          // 6*HDIM + HDIM (fused XG|PX width)
#define KCAT  2048          // 2*HDIM
#define NPAIR 32            // (2048/64) BK64 pairs total

// plane strides (elements)
#define PS_F  ((size_t)N_OBJ * FDIM)
#define PS_WA ((size_t)NALL * FDIM)
#define PS_WC ((size_t)G6 * KCAT)
#define PS_H  ((size_t)(N_OBJ + 1) * HDIM)
#define PS_XG ((size_t)N_OBJ * NALL)

// ---------------- scratch (static device globals; no allocation) -------------
__device__ float g_XGP[2 * PS_XG];                   // phase-A split-K slabs
__device__ float g_biaslr[G6];
__device__ float g_biasA[NALL];                      // b_iox | b_px
__device__ float g_C[(size_t)(N_OBJ + 1) * HDIM];
__device__ float g_H[(size_t)(N_OBJ + 1) * HDIM];
__device__ float g_Gh[(size_t)2048 * G6];            // level split-K slabs

// fp16 operand planes (single plane each side)
__device__ __half g_Fe [PS_F];                       // features
__device__ __half g_WAe[PS_WA];                      // [w_iox; w_px]
__device__ __half g_Wce[PS_WC];                      // [Wl | Wr]
__device__ __half g_He [PS_H];                       // hidden

// grid-barrier state for the persistent tail kernel
__device__ unsigned g_bar_count = 0;
__device__ unsigned g_bar_gen = 0;

// ---------------- helpers ----------------------------------------------------
__device__ __forceinline__ uint32_t smem_to_u32(const void* p) {
    uint32_t a;
    asm("{ .reg .u64 t; cvta.to.shared.u64 t, %1; cvt.u32.u64 %0, t; }" : "=r"(a) : "l"(p));
    return a;
}
__device__ __forceinline__ void ldmx4(uint32_t* d, uint32_t addr) {
    asm volatile("ldmatrix.sync.aligned.m8n8.x4.shared.b16 {%0,%1,%2,%3}, [%4];"
                 : "=r"(d[0]), "=r"(d[1]), "=r"(d[2]), "=r"(d[3]) : "r"(addr));
}
__device__ __forceinline__ void mma_f16(float* c, const uint32_t* a, const uint32_t* b) {
    asm volatile("mma.sync.aligned.m16n8k16.row.col.f32.f16.f16.f32 "
                 "{%0,%1,%2,%3}, {%4,%5,%6,%7}, {%8,%9}, {%0,%1,%2,%3};"
                 : "+f"(c[0]), "+f"(c[1]), "+f"(c[2]), "+f"(c[3])
                 : "r"(a[0]), "r"(a[1]), "r"(a[2]), "r"(a[3]), "r"(b[0]), "r"(b[1]));
}
__device__ __forceinline__ void cpasync16(uint32_t dst, const void* src) {
    asm volatile("cp.async.cg.shared.global [%0], [%1], 16;" :: "r"(dst), "l"(src));
}

// swizzle: 16B chunk x (0..3) within a 64B row r -> conflict-free for both
// cp.async stores and ldmatrix reads.
__device__ __forceinline__ uint32_t swz(int r, int x) {
    return (uint32_t)(r * 64 + ((x ^ ((r >> 1) & 3)) << 4));
}

__device__ __forceinline__ float sigm(float x) { return 1.f / (1.f + expf(-x)); }

// ---------------- merged expansion: all fp16 planes in one launch ------------
// ranges: [0, PS_F) -> Fe from features
//         [PS_F, PS_F + G6*FDIM) -> WAe[w_iox]
//         [.., +HDIM*FDIM) -> WAe[w_px part]
//         [.., +PS_WC) -> Wce from (wl | wr)
__global__ void expand_all_kernel(const float* __restrict__ features,
                                  const float* __restrict__ w_iox,
                                  const float* __restrict__ w_px,
                                  const float* __restrict__ wl,
                                  const float* __restrict__ wr)
{
    const size_t E0 = PS_F;
    const size_t E1 = E0 + (size_t)G6 * FDIM;
    const size_t E2 = E1 + (size_t)HDIM * FDIM;
    const size_t E3 = E2 + PS_WC;
    for (size_t i = (size_t)blockIdx.x * 256 + threadIdx.x; i < E3;
         i += (size_t)gridDim.x * 256) {
        if (i < E0) {
            g_Fe[i] = __float2half_rn(features[i]);
        } else if (i < E1) {
            size_t k = i - E0;
            g_WAe[k] = __float2half_rn(w_iox[k]);
        } else if (i < E2) {
            size_t k = i - E1;
            g_WAe[(size_t)G6 * FDIM + k] = __float2half_rn(w_px[k]);
        } else {
            size_t idx = i - E2;
            size_t j = idx >> 11;
            int k = (int)(idx & (KCAT - 1));
            float w = (k < HDIM) ? wl[j * HDIM + k] : wr[j * HDIM + (k - HDIM)];
            g_Wce[idx] = __float2half_rn(w);
        }
    }
}

// ---------------- prep: biases + sentinel rows -------------------------------
__global__ void prep_kernel(const float* __restrict__ bl, const float* __restrict__ br,
                            const float* __restrict__ bx, const float* __restrict__ bp)
{
    int idx = blockIdx.x * 256 + threadIdx.x;   // over NALL
    if (idx < G6) g_biaslr[idx] = bl[idx] + br[idx];
    if (idx < NALL) g_biasA[idx] = (idx < G6) ? bx[idx] : bp[idx - G6];
    if (idx < HDIM) {
        size_t s = (size_t)N_OBJ * HDIM + idx;
        g_C[s] = 0.f; g_H[s] = 0.f;
        g_He[s] = __float2half_rn(0.f);
    }
}

// ---------------- fp16 mma GEMM: C = A @ B^T (+bias on part 0) ---------------
// A, B: single fp16 planes, row stride 2048.
// Stage = BK64 = two 32-wide sub-tiles, 3 stages; BN=128, BM in {128, 64}.
// Split-K (non-uniform): part p handles pairs [p*ppp, min((p+1)*ppp, NPAIR)),
// writes slab C + p*M*N. Bias applied only by part 0. Deterministic.
template <int BM>
__global__ __launch_bounds__(256, 2) void gemm_hf(
    const __half* __restrict__ A, const __half* __restrict__ B,
    const float* __restrict__ bias, float* __restrict__ C, int M, int N, int ppp)
{
    constexpr int WCOLS = (BM == 128) ? 4 : 8;
    constexpr int WN = 128 / WCOLS;           // 32 / 16
    constexpr int NF = WN / 8;                // 4 / 2
    constexpr int ATB = BM * 64;              // A sub-tile bytes
    constexpr int SUB = ATB + 8192;           // A+B sub-tile
    constexpr int STAGE = 2 * SUB;            // BK64 stage bytes

    extern __shared__ char smem[];
    const uint32_t sb = smem_to_u32(smem);
    const int tid = threadIdx.x, lane = tid & 31, warp = tid >> 5;
    const int wr_ = warp / WCOLS, wc_ = warp % WCOLS;

    const int part = blockIdx.z;
    C += (size_t)part * M * N;
    if (part != 0) bias = nullptr;
    const int p0 = part * ppp;
    int cnt = NPAIR - p0; if (cnt > ppp) cnt = ppp;   // non-uniform tail part

    // ---- L2-aware tile swizzle (within a part) ----
    const int tiles_n = gridDim.x, tiles_m = gridDim.y;
    int lid = blockIdx.y * tiles_n + blockIdx.x;
    const int GRP = 8;
    int per_group = GRP * tiles_m;
    int grp = lid / per_group, rem = lid - grp * per_group;
    int nt0 = grp * GRP;
    int gn = tiles_n - nt0; if (gn > GRP) gn = GRP;
    int nt = nt0 + rem % gn;
    int mt = rem / gn;
    const int row0 = mt * BM, col0 = nt * 128;

    // ldmatrix lane geometry
    const int lrow = ((lane >> 3) & 1) * 8 + (lane & 7);
    const int lcol = lane >> 4;

    // cp.async op coords
    const int r_op0 = tid >> 2,         ch0 = tid & 3;
    const int r_op1 = (tid + 256) >> 2, ch1 = tid & 3;

    float acc[4][NF][4];
#pragma unroll
    for (int a = 0; a < 4; a++)
#pragma unroll
        for (int b = 0; b < NF; b++)
#pragma unroll
            for (int t = 0; t < 4; t++) acc[a][b][t] = 0.f;

    // load one 32-wide k-chunk c into sub-slot (A @ off, B @ off+ATB)
    auto load_sub = [&](int c, uint32_t off) {
        const __half* Ab = A + (size_t)c * 32;
        const __half* Bb = B + (size_t)c * 32;
        uint32_t sA = sb + off, sBm = sA + ATB;
        cpasync16(sA + swz(r_op0, ch0), Ab + (size_t)(row0 + r_op0) * 2048 + ch0 * 8);
        if (BM == 128)
            cpasync16(sA + swz(r_op1, ch1), Ab + (size_t)(row0 + r_op1) * 2048 + ch1 * 8);
        cpasync16(sBm + swz(r_op0, ch0), Bb + (size_t)(col0 + r_op0) * 2048 + ch0 * 8);
        cpasync16(sBm + swz(r_op1, ch1), Bb + (size_t)(col0 + r_op1) * 2048 + ch1 * 8);
    };
    auto load_pair = [&](int p, int st) {
        load_sub(2 * p,     (uint32_t)(st * STAGE));
        load_sub(2 * p + 1, (uint32_t)(st * STAGE + SUB));
        asm volatile("cp.async.commit_group;" ::: "memory");
    };
    // fragment load for k16 step kk (0..3) of stage st
    auto ldfrag = [&](int st, int kk, uint32_t af[4][4], uint32_t bq[2][4]) {
        uint32_t sA = sb + st * STAGE + (kk >> 1) * SUB;
        uint32_t sBm = sA + ATB;
        int kl = (kk & 1) * 2 + lcol;
#pragma unroll
        for (int mf = 0; mf < 4; mf++) {
            int r = wr_ * 64 + mf * 16 + lrow;
            ldmx4(af[mf], sA + swz(r, kl));
        }
#pragma unroll
        for (int bh = 0; bh < WN / 16; bh++) {
            int r = wc_ * WN + bh * 16 + lrow;
            ldmx4(bq[bh], sBm + swz(r, kl));
        }
    };

    load_pair(p0, 0);
    if (cnt > 1) load_pair(p0 + 1, 1);

    uint32_t fA[2][4][4], fB[2][2][4];

    for (int i = 0; i < cnt; i++) {
        int st = i % 3;
        if (i + 2 < cnt) {
            asm volatile("cp.async.wait_group 1;" ::: "memory");
        } else {
            asm volatile("cp.async.wait_group 0;" ::: "memory");   // tail drain
        }
        __syncthreads();
        if (i + 2 < cnt) load_pair(p0 + i + 2, (i + 2) % 3);

        ldfrag(st, 0, fA[0], fB[0]);
#pragma unroll
        for (int kk = 0; kk < 4; kk++) {
            if (kk < 3) ldfrag(st, kk + 1, fA[(kk + 1) & 1], fB[(kk + 1) & 1]);
            uint32_t (*af)[4] = fA[kk & 1];
            uint32_t (*bq)[4] = fB[kk & 1];
#pragma unroll
            for (int mf = 0; mf < 4; mf++)
#pragma unroll
                for (int nf = 0; nf < NF; nf++) {
                    uint32_t b2[2] = { bq[nf >> 1][nf & 1], bq[nf >> 1][2 + (nf & 1)] };
                    mma_f16(acc[mf][nf], af[mf], b2);
                }
        }
    }

    // ---- epilogue ----
#pragma unroll
    for (int mf = 0; mf < 4; mf++) {
#pragma unroll
        for (int nf = 0; nf < NF; nf++) {
            int r  = row0 + wr_ * 64 + mf * 16 + (lane >> 2);
            int cb = col0 + wc_ * WN + nf * 8 + (lane & 3) * 2;
            float b0 = bias ? bias[cb] : 0.f;
            float b1 = bias ? bias[cb + 1] : 0.f;
            if (r < M) {
                C[(size_t)r * N + cb]     = acc[mf][nf][0] + b0;
                C[(size_t)r * N + cb + 1] = acc[mf][nf][1] + b1;
            }
            if (r + 8 < M) {
                C[(size_t)(r + 8) * N + cb]     = acc[mf][nf][2] + b0;
                C[(size_t)(r + 8) * N + cb + 1] = acc[mf][nf][3] + b1;
            }
        }
    }
}

// ---------------- tiny-M GEMM (M<=16): A fp32, B fp16; warp per column -------
__global__ void gemm_small_h(const float* __restrict__ A, const __half* __restrict__ B,
                             float* __restrict__ C, int M, int N, int K)
{
    int warp = threadIdx.x >> 5, lane = threadIdx.x & 31;
    int n = blockIdx.x * 8 + warp;
    if (n >= N) return;
    float acc[16];
#pragma unroll
    for (int m = 0; m < 16; m++) acc[m] = 0.f;
    const __half* Brow = B + (size_t)n * K;
    for (int k = lane * 8; k < K; k += 256) {
        uint4 braw = *(const uint4*)(Brow + k);
        float2 b01 = __half22float2(*(__half2*)&braw.x);
        float2 b23 = __half22float2(*(__half2*)&braw.y);
        float2 b45 = __half22float2(*(__half2*)&braw.z);
        float2 b67 = __half22float2(*(__half2*)&braw.w);
#pragma unroll
        for (int m = 0; m < 16; m++) {
            if (m < M) {
                float4 a0 = *(const float4*)(A + (size_t)m * K + k);
                float4 a1 = *(const float4*)(A + (size_t)m * K + k + 4);
                acc[m] += a0.x * b01.x + a0.y * b01.y + a0.z * b23.x + a0.w * b23.y
                        + a1.x * b45.x + a1.y * b45.y + a1.z * b67.x + a1.w * b67.y;
            }
        }
    }
#pragma unroll
    for (int m = 0; m < 16; m++) {
        if (m < M) {
            float v = acc[m];
#pragma unroll
            for (int off = 16; off; off >>= 1) v += __shfl_xor_sync(~0u, v, off);
            if (lane == 0) C[(size_t)m * N + n] = v;
        }
    }
}

// ---------------- pointwise LSTM cell (reads both phase-A slabs) -------------
__global__ void pointwise(int s, int M, const float* __restrict__ Gh,
                          int nparts, int pstride, float* __restrict__ out)
{
    int idx = blockIdx.x * blockDim.x + threadIdx.x;
    if (idx >= M * HDIM) return;
    int m = idx >> 10;
    int j = idx & (HDIM - 1);
    int n = s + m;

    const float* xg0 = g_XGP + (size_t)n * NALL;          // slab 0 (with bias)
    const float* xg1 = xg0 + PS_XG;                       // slab 1
    float g[6];
#pragma unroll
    for (int t = 0; t < 6; t++) {
        int o = t * HDIM + j;
        float v = xg0[o] + xg1[o] + g_biaslr[o];
        for (int p = 0; p < nparts; p++)
            v += Gh[(size_t)p * pstride + (size_t)m * G6 + o];
        g[t] = v;
    }
    float ig = sigm(g[0]), og = sigm(g[1]);
    float fl = sigm(g[2]), fr = sigm(g[3]);
    float u  = tanhf(g[4]), rr = sigm(g[5]);

    int l = 2 * n + 1; if (l > N_OBJ) l = N_OBJ;
    int r = 2 * n + 2; if (r > N_OBJ) r = N_OBJ;

    float c = ig * u + fl * g_C[(size_t)l * HDIM + j] + fr * g_C[(size_t)r * HDIM + j];
    float h = og * tanhf(c);
    float hf = rr * h + (1.f - rr) * (xg0[G6 + j] + xg1[G6 + j]);   // px fused

    size_t o = (size_t)n * HDIM + j;
    g_C[o] = c;
    g_H[o] = hf;
    out[o] = hf;
    g_He[o] = __float2half_rn(hf);
}

// ---------------- persistent fused tail: levels M=16..1 ----------------------
__device__ __forceinline__ void grid_barrier()
{
    __syncthreads();
    if (threadIdx.x == 0) {
        __threadfence();
        unsigned gen = *((volatile unsigned*)&g_bar_gen);
        unsigned ticket = atomicAdd(&g_bar_count, 1);
        if (ticket == gridDim.x - 1) {
            g_bar_count = 0;
            __threadfence();
            atomicAdd(&g_bar_gen, 1);
        } else {
            while (*((volatile unsigned*)&g_bar_gen) == gen) __nanosleep(64);
        }
        __threadfence();
    }
    __syncthreads();
}

__global__ __launch_bounds__(256, 2) void tail_kernel(float* __restrict__ out)
{
    const int tid = threadIdx.x;
    const int warp = tid >> 5, lane = tid & 31;
    const int sv[5] = {15, 7, 3, 1, 0};
    const int Mv[5] = {16, 8, 4, 2, 1};

    for (int li = 0; li < 5; li++) {
        const int s = sv[li], M = Mv[li];
        const float* A = g_H + (size_t)(2 * s + 1) * HDIM;   // [M rows x 2048]

        // ---- GEMM: g_Gh[m][n] = sum_k A[m][k] * Wce[n][k] ----
        for (int n = blockIdx.x * 8 + warp; n < G6; n += gridDim.x * 8) {
            float acc[16];
#pragma unroll
            for (int m = 0; m < 16; m++) acc[m] = 0.f;
            const __half* Brow = g_Wce + (size_t)n * KCAT;
            for (int k = lane * 8; k < KCAT; k += 256) {
                uint4 braw = *(const uint4*)(Brow + k);
                float2 b01 = __half22float2(*(__half2*)&braw.x);
                float2 b23 = __half22float2(*(__half2*)&braw.y);
                float2 b45 = __half22float2(*(__half2*)&braw.z);
                float2 b67 = __half22float2(*(__half2*)&braw.w);
#pragma unroll
                for (int m = 0; m < 16; m++) {
                    if (m < M) {
                        float4 a0 = *(const float4*)(A + (size_t)m * KCAT + k);
                        float4 a1 = *(const float4*)(A + (size_t)m * KCAT + k + 4);
                        acc[m] += a0.x * b01.x + a0.y * b01.y + a0.z * b23.x + a0.w * b23.y
                                + a1.x * b45.x + a1.y * b45.y + a1.z * b67.x + a1.w * b67.y;
                    }
                }
            }
#pragma unroll
            for (int m = 0; m < 16; m++) {
                if (m < M) {
                    float v = acc[m];
#pragma unroll
                    for (int off = 16; off; off >>= 1) v += __shfl_xor_sync(~0u, v, off);
                    if (lane == 0) g_Gh[(size_t)m * G6 + n] = v;
                }
            }
        }
        grid_barrier();

        // ---- pointwise ----
        for (int idx = blockIdx.x * 256 + tid; idx < M * HDIM; idx += gridDim.x * 256) {
            int m = idx >> 10;
            int j = idx & (HDIM - 1);
            int n = s + m;
            const float* xg0 = g_XGP + (size_t)n * NALL;
            const float* xg1 = xg0 + PS_XG;
            float g[6];
#pragma unroll
            for (int t = 0; t < 6; t++) {
                int o = t * HDIM + j;
                g[t] = xg0[o] + xg1[o] + g_biaslr[o] + g_Gh[(size_t)m * G6 + o];
            }
            float ig = sigm(g[0]), og = sigm(g[1]);
            float fl = sigm(g[2]), fr = sigm(g[3]);
            float u  = tanhf(g[4]), rr = sigm(g[5]);
            int l = 2 * n + 1, r = 2 * n + 2;        // always <= 2046 here
            float c = ig * u + fl * g_C[(size_t)l * HDIM + j]
                             + fr * g_C[(size_t)r * HDIM + j];
            float h = og * tanhf(c);
            float hf = rr * h + (1.f - rr) * (xg0[G6 + j] + xg1[G6 + j]);
            size_t o = (size_t)n * HDIM + j;
            g_C[o] = c;
            g_H[o] = hf;
            out[o] = hf;
        }
        grid_barrier();
    }
}

// ---------------- launcher ---------------------------------------------------
extern "C" void kernel_launch(void* const* d_in, const int* in_sizes, int n_in,
                              void* d_out, int out_size)
{
    const float* features = (const float*)d_in[0];
    const float* w_iox    = (const float*)d_in[1];
    const float* b_iox    = (const float*)d_in[2];
    const float* w_l      = (const float*)d_in[3];
    const float* b_l      = (const float*)d_in[4];
    const float* w_r      = (const float*)d_in[5];
    const float* b_r      = (const float*)d_in[6];
    const float* w_px     = (const float*)d_in[7];
    const float* b_px     = (const float*)d_in[8];
    float* out = (float*)d_out;

    float *XGP, *Gh, *Htab, *biasA;
    __half *Fe, *WAe, *Wce, *He;
    cudaGetSymbolAddress((void**)&XGP,   g_XGP);
    cudaGetSymbolAddress((void**)&Gh,    g_Gh);
    cudaGetSymbolAddress((void**)&Htab,  g_H);
    cudaGetSymbolAddress((void**)&biasA, g_biasA);
    cudaGetSymbolAddress((void**)&Fe,    g_Fe);
    cudaGetSymbolAddress((void**)&WAe,   g_WAe);
    cudaGetSymbolAddress((void**)&Wce,   g_Wce);
    cudaGetSymbolAddress((void**)&He,    g_He);

    const int SMEM_128 = 3 * 32768;
    const int SMEM_64  = 3 * 24576;
    cudaFuncSetAttribute(gemm_hf<128>, cudaFuncAttributeMaxDynamicSharedMemorySize, SMEM_128);
    cudaFuncSetAttribute(gemm_hf<64>,  cudaFuncAttributeMaxDynamicSharedMemorySize, SMEM_64);

    // prep + merged fp16 expansion (one launch)
    prep_kernel<<<(NALL + 255) / 256, 256>>>(b_l, b_r, b_iox, b_px);
    expand_all_kernel<<<4096, 256>>>(features, w_iox, w_px, w_l, w_r);

    // phase A: fused [XG | PX] GEMM, N = 7168, split-K=2 (wave packing)
    gemm_hf<128><<<dim3(NALL / 128, N_OBJ / 128, 2), 256, SMEM_128>>>(
        Fe, WAe, biasA, XGP, N_OBJ, NALL, NPAIR / 2);

    // leaves
    pointwise<<<(1024 * HDIM + 255) / 256, 256>>>(1024, 1024, nullptr, 0, 0, out);

    // node 1023 (single; A fp32 rows 2047 + sentinel 2048, B fp16)
    gemm_small_h<<<G6 / 8, 256>>>(Htab + (size_t)2047 * HDIM, Wce, Gh, 1, G6, KCAT);
    pointwise<<<(1 * HDIM + 255) / 256, 256>>>(1023, 1, Gh, 1, 0, out);

    // big internal wavefronts, deterministic non-uniform split-K (wave-packed)
    struct Lv { int s, M, KS, BM; };
    const Lv big[5] = { {511, 512, 3, 128}, {255, 256, 3, 128}, {127, 128, 6, 128},
                        {63, 64, 6, 64}, {31, 32, 6, 64} };
    for (int li = 0; li < 5; li++) {
        int s = big[li].s, M = big[li].M, KS = big[li].KS;
        int ppp = (NPAIR + KS - 1) / KS;
        const __half* Ab = He + (size_t)(2 * s + 1) * HDIM;
        if (big[li].BM == 128) {
            int Mtiles = (M + 127) / 128;
            gemm_hf<128><<<dim3(G6 / 128, Mtiles, KS), 256, SMEM_128>>>(
                Ab, Wce, nullptr, Gh, M, G6, ppp);
        } else {
            gemm_hf<64><<<dim3(G6 / 128, 1, KS), 256, SMEM_64>>>(
                Ab, Wce, nullptr, Gh, M, G6, ppp);
        }
        pointwise<<<(M * HDIM + 255) / 256, 256>>>(s, M, Gh, KS, M * G6, out);
    }

    // fused persistent tail: levels M=16,8,4,2,1
    tail_kernel<<<296, 256>>>(out);
}